// round 1
// baseline (speedup 1.0000x reference)
#include <cuda_runtime.h>
#include <math.h>

// Problem constants
#define Bn 128
#define Tn 256
#define Sn 256
#define Hn 512
#define En 256
#define Vn 10000
#define H2 1024   // 2H
#define H4 2048   // 4H

// ---------------- scratch (static device memory; no allocs allowed) ----------------
__device__ float g_h0[Bn * Hn];
__device__ float g_c0[Bn * Hn];
__device__ float g_qproj[Bn * Hn];
__device__ float g_scores[Bn * Sn];
__device__ float g_context[Bn * H2];
__device__ float g_gconst[Bn * H4];
__device__ float g_ctxP[Bn * Hn];
__device__ float g_embW[(size_t)Vn * H4];        // emb @ W_ih[:, :E].T   (82 MB, L2-resident)
__device__ float g_embP[(size_t)Vn * Hn];        // emb @ pre_W[:, :E].T  (20 MB)
__device__ float g_big[(size_t)Bn * Sn * Hn];    // proj_key, then reused for h  (67 MB)

__device__ __forceinline__ float sigf(float x) { return 1.f / (1.f + expf(-x)); }

__device__ __forceinline__ float warp_red(float v) {
    #pragma unroll
    for (int o = 16; o; o >>= 1) v += __shfl_down_sync(0xffffffffu, v, o);
    return v;
}

// ---------------- generic warp-per-output  out[b,n] = act( x[b,:] . W[n,:] + bias[n] ) ----
__global__ void vecmatT_kernel(const float* __restrict__ X,
                               const float* __restrict__ W, int ldw,
                               const float* __restrict__ bias,
                               float* __restrict__ out, int N, int K, int act)
{
    int warp = threadIdx.x >> 5, lane = threadIdx.x & 31;
    int n = blockIdx.x * 8 + warp;
    int b = blockIdx.y;
    const float* x = X + (size_t)b * K;
    const float* w = W + (size_t)n * ldw;
    float s = 0.f;
    for (int k = lane; k < K; k += 32) s += x[k] * w[k];
    s = warp_red(s);
    if (lane == 0) {
        if (bias) s += bias[n];
        if (act)  s = tanhf(s);
        out[(size_t)b * N + n] = s;
    }
}

// ---------------- gconst[b,n] = ctx.W_ih[:,E:] + h0.W_hh + b_ih + b_hh -----------------
__global__ void gconst_kernel(const float* __restrict__ W_ih,
                              const float* __restrict__ W_hh,
                              const float* __restrict__ b_ih,
                              const float* __restrict__ b_hh)
{
    int warp = threadIdx.x >> 5, lane = threadIdx.x & 31;
    int n = blockIdx.x * 8 + warp;     // 0..2047
    int b = blockIdx.y;
    const float* ctx = g_context + (size_t)b * H2;
    const float* h0  = g_h0 + (size_t)b * Hn;
    const float* wi  = W_ih + (size_t)n * (En + H2) + En;
    const float* wh  = W_hh + (size_t)n * Hn;
    float s = 0.f;
    for (int k = lane; k < H2; k += 32) s += ctx[k] * wi[k];
    for (int k = lane; k < Hn; k += 32) s += h0[k] * wh[k];
    s = warp_red(s);
    if (lane == 0) g_gconst[(size_t)b * H4 + n] = s + b_ih[n] + b_hh[n];
}

// ---------------- scores[b,s] = sum_h tanh(PK + qproj) * eW, masked --------------------
__global__ void scores_kernel(const float* __restrict__ eW,
                              const int* __restrict__ srcpos)
{
    int warp = threadIdx.x >> 5, lane = threadIdx.x & 31;
    int row = blockIdx.x * 8 + warp;   // b*Sn + s
    int b = row >> 8;
    const float* pk = g_big + (size_t)row * Hn;
    const float* q  = g_qproj + (size_t)b * Hn;
    float s = 0.f;
    for (int h = lane; h < Hn; h += 32) s += tanhf(pk[h] + q[h]) * eW[h];
    s = warp_red(s);
    if (lane == 0) g_scores[row] = (srcpos[row] != 0) ? s : -1e9f;
}

// ---------------- softmax over S (in place) --------------------------------------------
__global__ void softmax_kernel()
{
    __shared__ float sm[8];
    int b = blockIdx.x, t = threadIdx.x, w = t >> 5, l = t & 31;
    float v = g_scores[b * Sn + t];
    float m = v;
    #pragma unroll
    for (int o = 16; o; o >>= 1) m = fmaxf(m, __shfl_xor_sync(0xffffffffu, m, o));
    if (l == 0) sm[w] = m;
    __syncthreads();
    m = sm[0];
    #pragma unroll
    for (int i = 1; i < 8; i++) m = fmaxf(m, sm[i]);
    __syncthreads();
    float e = expf(v - m);
    float s = e;
    #pragma unroll
    for (int o = 16; o; o >>= 1) s += __shfl_xor_sync(0xffffffffu, s, o);
    if (l == 0) sm[w] = s;
    __syncthreads();
    s = 0.f;
    #pragma unroll
    for (int i = 0; i < 8; i++) s += sm[i];
    g_scores[b * Sn + t] = e / s;
}

// ---------------- context[b,d] = sum_s alphas[b,s] * enc[b,s,d] ------------------------
__global__ void context_kernel(const float* __restrict__ enc)
{
    __shared__ float a[Sn];
    int b = blockIdx.x;
    int d = blockIdx.y * 256 + threadIdx.x;
    a[threadIdx.x] = g_scores[b * Sn + threadIdx.x];
    __syncthreads();
    const float* e = enc + (size_t)b * Sn * H2 + d;
    float s = 0.f;
    #pragma unroll 4
    for (int sS = 0; sS < Sn; sS++) s += a[sS] * e[(size_t)sS * H2];
    g_context[(size_t)b * H2 + d] = s;
}

// ---------------- gates -> h  (LSTM cell, no recurrence) --------------------------------
__global__ void gates_kernel(const int* __restrict__ tgt)
{
    int row = blockIdx.x;          // b*Tn + t
    int t = threadIdx.x;           // 0..511
    int b = row >> 8;
    int tok = tgt[row];
    const float* ew = g_embW + (size_t)tok * H4;
    const float* gc = g_gconst + (size_t)b * H4;
    float i_ = ew[t]          + gc[t];
    float f_ = ew[t + Hn]     + gc[t + Hn];
    float gg = ew[t + 2 * Hn] + gc[t + 2 * Hn];
    float o_ = ew[t + 3 * Hn] + gc[t + 3 * Hn];
    float c = sigf(f_) * g_c0[(size_t)b * Hn + t] + sigf(i_) * tanhf(gg);
    float h = sigf(o_) * tanhf(c);
    g_big[(size_t)row * Hn + t] = h;
}

// ---------------- tiled SGEMM-NT: C[m,n] = sum_k A[m,k] * W[n,k]  (+ epilogue) ----------
template<bool GUARD_M, bool EPI>
__global__ __launch_bounds__(256)
void sgemm_nt(const float* __restrict__ A, int lda,
              const float* __restrict__ W, int ldw,
              float* __restrict__ C, int ldc,
              int M, int K,
              const int* __restrict__ tok,
              const float* __restrict__ embP,
              const float* __restrict__ ctxP)
{
    __shared__ float As[16][128];
    __shared__ float Bs[16][128];
    const int tid = threadIdx.x;
    const int tr = tid >> 4;             // 0..15
    const int tc = tid & 15;             // 0..15
    const int m0 = blockIdx.y * 128;
    const int n0 = blockIdx.x * 128;
    const int lRow = tid >> 2;           // 0..63
    const int lCol = (tid & 3) << 2;     // 0,4,8,12

    float acc[8][8];
    #pragma unroll
    for (int i = 0; i < 8; i++)
        #pragma unroll
        for (int j = 0; j < 8; j++) acc[i][j] = 0.f;

    const float* Aptr = A + (size_t)(m0 + lRow) * lda + lCol;
    const float* Wptr = W + (size_t)(n0 + lRow) * ldw + lCol;

    for (int k0 = 0; k0 < K; k0 += 16) {
        #pragma unroll
        for (int r = 0; r < 2; r++) {
            float4 v = make_float4(0.f, 0.f, 0.f, 0.f);
            if (!GUARD_M || (m0 + lRow + r * 64) < M)
                v = *reinterpret_cast<const float4*>(Aptr + (size_t)r * 64 * lda + k0);
            As[lCol + 0][lRow + r * 64] = v.x;
            As[lCol + 1][lRow + r * 64] = v.y;
            As[lCol + 2][lRow + r * 64] = v.z;
            As[lCol + 3][lRow + r * 64] = v.w;
        }
        #pragma unroll
        for (int r = 0; r < 2; r++) {
            float4 v = *reinterpret_cast<const float4*>(Wptr + (size_t)r * 64 * ldw + k0);
            Bs[lCol + 0][lRow + r * 64] = v.x;
            Bs[lCol + 1][lRow + r * 64] = v.y;
            Bs[lCol + 2][lRow + r * 64] = v.z;
            Bs[lCol + 3][lRow + r * 64] = v.w;
        }
        __syncthreads();
        #pragma unroll
        for (int k = 0; k < 16; k++) {
            float a[8], bb[8];
            #pragma unroll
            for (int i = 0; i < 8; i++) a[i] = As[k][tr * 8 + i];
            #pragma unroll
            for (int j = 0; j < 8; j++) bb[j] = Bs[k][tc * 8 + j];
            #pragma unroll
            for (int i = 0; i < 8; i++)
                #pragma unroll
                for (int j = 0; j < 8; j++)
                    acc[i][j] += a[i] * bb[j];
        }
        __syncthreads();
    }

    #pragma unroll
    for (int i = 0; i < 8; i++) {
        int row = m0 + tr * 8 + i;
        if (GUARD_M && row >= M) return;   // rows ascend with i
        const float* ep = nullptr;
        const float* cp = nullptr;
        if (EPI) {
            ep = embP + (size_t)tok[row] * Hn;
            cp = ctxP + (size_t)(row >> 8) * Hn;   // b = row / Tn
        }
        #pragma unroll
        for (int j = 0; j < 8; j++) {
            int col = n0 + tc * 8 + j;
            float v = acc[i][j];
            if (EPI) v += ep[col] + cp[col];
            C[(size_t)row * ldc + col] = v;
        }
    }
}

// =========================================================================================
extern "C" void kernel_launch(void* const* d_in, const int* in_sizes, int n_in,
                              void* d_out, int out_size)
{
    const int*   tgt     = (const int*)  d_in[0];
    const float* enc     = (const float*)d_in[1];
    const float* eh      = (const float*)d_in[2];
    const float* ec      = (const float*)d_in[3];
    const int*   srcpos  = (const int*)  d_in[4];
    const float* emb     = (const float*)d_in[5];
    const float* key_W   = (const float*)d_in[6];
    const float* query_W = (const float*)d_in[7];
    const float* eW      = (const float*)d_in[8];
    const float* W_ih    = (const float*)d_in[9];
    const float* W_hh    = (const float*)d_in[10];
    const float* b_ih    = (const float*)d_in[11];
    const float* b_hh    = (const float*)d_in[12];
    const float* bhW     = (const float*)d_in[13];
    const float* bhb     = (const float*)d_in[14];
    const float* bcW     = (const float*)d_in[15];
    const float* bcb     = (const float*)d_in[16];
    const float* pre_W   = (const float*)d_in[17];
    float* out = (float*)d_out;

    float *p_h0, *p_c0, *p_qproj, *p_context, *p_ctxP, *p_embW, *p_embP, *p_big;
    cudaGetSymbolAddress((void**)&p_h0, g_h0);
    cudaGetSymbolAddress((void**)&p_c0, g_c0);
    cudaGetSymbolAddress((void**)&p_qproj, g_qproj);
    cudaGetSymbolAddress((void**)&p_context, g_context);
    cudaGetSymbolAddress((void**)&p_ctxP, g_ctxP);
    cudaGetSymbolAddress((void**)&p_embW, g_embW);
    cudaGetSymbolAddress((void**)&p_embP, g_embP);
    cudaGetSymbolAddress((void**)&p_big, g_big);

    // 1) bridges: h0 = tanh(eh @ bridge_hW.T + hb), c0 likewise
    vecmatT_kernel<<<dim3(Hn / 8, Bn), 256>>>(eh, bhW, H2, bhb, p_h0, Hn, H2, 1);
    vecmatT_kernel<<<dim3(Hn / 8, Bn), 256>>>(ec, bcW, H2, bcb, p_c0, Hn, H2, 1);
    // 2) qproj = h0 @ query_W.T
    vecmatT_kernel<<<dim3(Hn / 8, Bn), 256>>>(p_h0, query_W, Hn, nullptr, p_qproj, Hn, Hn, 0);
    // 3) PK = enc2d @ key_W.T   (32768 x 512 x 1024)  -> g_big
    sgemm_nt<false, false><<<dim3(Hn / 128, (Bn * Sn) / 128), 256>>>(
        enc, H2, key_W, H2, p_big, Hn, Bn * Sn, H2, nullptr, nullptr, nullptr);
    // 4) scores = sum_h tanh(PK + qproj) * eW, masked
    scores_kernel<<<(Bn * Sn) / 8, 256>>>(eW, srcpos);
    // 5) softmax over S
    softmax_kernel<<<Bn, Sn>>>();
    // 6) context = alphas . enc
    context_kernel<<<dim3(Bn, H2 / 256), 256>>>(enc);
    // 7) per-b gate constant and ctxP
    gconst_kernel<<<dim3(H4 / 8, Bn), 256>>>(W_ih, W_hh, b_ih, b_hh);
    vecmatT_kernel<<<dim3(Hn / 8, Bn), 256>>>(p_context, pre_W + En + Hn, En + Hn + H2,
                                              nullptr, p_ctxP, Hn, H2, 0);
    // 8) vocab-level precomputes: embW = emb @ W_ih[:, :E].T ; embP = emb @ pre_W[:, :E].T
    sgemm_nt<true, false><<<dim3(H4 / 128, (Vn + 127) / 128), 256>>>(
        emb, En, W_ih, En + H2, p_embW, H4, Vn, En, nullptr, nullptr, nullptr);
    sgemm_nt<true, false><<<dim3(Hn / 128, (Vn + 127) / 128), 256>>>(
        emb, En, pre_W, En + Hn + H2, p_embP, Hn, Vn, En, nullptr, nullptr, nullptr);
    // 9) LSTM cell -> h   (overwrites g_big; PK already consumed)
    gates_kernel<<<Bn * Tn, Hn>>>(tgt);
    // 10) out = h @ pre_W[:, E:E+H].T + embP[tok] + ctxP[b]
    sgemm_nt<false, true><<<dim3(Hn / 128, (Bn * Tn) / 128), 256>>>(
        p_big, Hn, pre_W + En, En + Hn + H2, out, Hn, Bn * Tn, Hn, tgt, p_embP, p_ctxP);

    (void)in_sizes; (void)n_in; (void)out_size;
}

// round 4
// speedup vs baseline: 2.1051x; 2.1051x over previous
#include <cuda_runtime.h>
#include <cuda_bf16.h>
#include <math.h>
#include <stdint.h>

#define Bn 128
#define Tn 256
#define Sn 256
#define Hn 512
#define En 256
#define Vn 10000
#define H2 1024
#define H4 2048

typedef __nv_bfloat16 bf16;
typedef __nv_bfloat162 bf162;

// ---------------- fp32 scratch ----------------
__device__ float g_h0[Bn * Hn];
__device__ float g_c0[Bn * Hn];
__device__ float g_qproj[Bn * Hn];
__device__ float g_scores[Bn * Sn];
__device__ float g_context[Bn * H2];
__device__ float g_gconst[Bn * H4];
__device__ float g_ctxP[Bn * Hn];
__device__ float g_xcat[Bn * 1536];
__device__ float g_wcat[(size_t)H4 * 1536];
__device__ float g_embW[(size_t)Vn * H4];
__device__ float g_embP[(size_t)Vn * Hn];
__device__ float g_big[(size_t)Bn * Sn * Hn];

// ---------------- split-bf16 (K'=3K) scratch ----------------
__device__ bf16 g_emb3[(size_t)Vn * 768];
__device__ bf16 g_Wih3[(size_t)H4 * 768];
__device__ bf16 g_preWe3[(size_t)Hn * 768];
__device__ bf16 g_key3[(size_t)Hn * 3072];
__device__ bf16 g_enc3[(size_t)Bn * Sn * 3072];
__device__ bf16 g_bhW3[(size_t)Hn * 3072];
__device__ bf16 g_bcW3[(size_t)Hn * 3072];
__device__ bf16 g_qW3[(size_t)Hn * 1536];
__device__ bf16 g_eh3[(size_t)Bn * 3072];
__device__ bf16 g_ec3[(size_t)Bn * 3072];
__device__ bf16 g_h03[(size_t)Bn * 1536];
__device__ bf16 g_ctx3[(size_t)Bn * 3072];
__device__ bf16 g_xcat3[(size_t)Bn * 4608];
__device__ bf16 g_wcat3[(size_t)H4 * 4608];
__device__ bf16 g_preWh3[(size_t)Hn * 1536];
__device__ bf16 g_preWc3[(size_t)Hn * 3072];
__device__ bf16 g_h3[(size_t)Bn * Tn * 1536];

__device__ __forceinline__ float sigf(float x) { return 1.f / (1.f + expf(-x)); }
__device__ __forceinline__ float warp_red(float v) {
    #pragma unroll
    for (int o = 16; o; o >>= 1) v += __shfl_down_sync(0xffffffffu, v, o);
    return v;
}

// ================= PTX helpers (portable sm_80+ subset) =================
__device__ __forceinline__ uint32_t smem_u32(const void* p) {
    uint32_t a;
    asm("{ .reg .u64 t; cvta.to.shared.u64 t, %1; cvt.u32.u64 %0, t; }" : "=r"(a) : "l"(p));
    return a;
}
__device__ __forceinline__ void cp16(uint32_t dst, const void* src) {
    asm volatile("cp.async.cg.shared.global [%0], [%1], 16;" :: "r"(dst), "l"(src) : "memory");
}
__device__ __forceinline__ void ldsm4(uint32_t* r, uint32_t addr) {
    asm volatile("ldmatrix.sync.aligned.m8n8.x4.shared.b16 {%0,%1,%2,%3}, [%4];"
                 : "=r"(r[0]), "=r"(r[1]), "=r"(r[2]), "=r"(r[3]) : "r"(addr));
}
__device__ __forceinline__ void ldsm2(uint32_t* r, uint32_t addr) {
    asm volatile("ldmatrix.sync.aligned.m8n8.x2.shared.b16 {%0,%1}, [%2];"
                 : "=r"(r[0]), "=r"(r[1]) : "r"(addr));
}
__device__ __forceinline__ void mma16(float* c, const uint32_t* a, const uint32_t* b) {
    asm volatile("mma.sync.aligned.m16n8k16.row.col.f32.bf16.bf16.f32 "
                 "{%0,%1,%2,%3}, {%4,%5,%6,%7}, {%8,%9}, {%0,%1,%2,%3};"
                 : "+f"(c[0]), "+f"(c[1]), "+f"(c[2]), "+f"(c[3])
                 : "r"(a[0]), "r"(a[1]), "r"(a[2]), "r"(a[3]), "r"(b[0]), "r"(b[1]));
}

// ================= split-bf16 mma.sync GEMM-NT =================
// C[m,n] = sum_k3 A3[m,k3] * W3[n,k3]   (K'=3K expansion already applied)
// 128x128 CTA tile, KC=64 bf16 per chunk (128B rows), K3 % 64 == 0
#define NSTAGE 3
#define STAGE_BYTES 32768          // A 16KB + B 16KB
#define SMEM_DYN (NSTAGE * STAGE_BYTES)

__device__ __forceinline__ void load_tiles(uint32_t base,
                                           const bf16* __restrict__ A, int lda,
                                           const bf16* __restrict__ W, int ldw,
                                           int m0, int n0, int k0, int M, bool guard, int tid)
{
    uint32_t ab = base, bb = base + 16384u;
    #pragma unroll
    for (int i = 0; i < 4; i++) {
        int c = tid + i * 256;
        int row = c >> 3, c16 = c & 7;
        uint32_t off = (uint32_t)(row * 128) + (uint32_t)((c16 ^ (row & 7)) << 4);
        int ar = m0 + row;
        if (guard && ar >= M) ar = M - 1;
        cp16(ab + off, A + (size_t)ar * lda + k0 + c16 * 8);
        cp16(bb + off, W + (size_t)(n0 + row) * ldw + k0 + c16 * 8);
    }
    asm volatile("cp.async.commit_group;" ::: "memory");
}

// EPI: 0 = none; 1 = +embP[tok[row]] + ctxP[row>>8]; 2 = tanh(acc + bias[col])
template<bool GUARD, int EPI>
__global__ __launch_bounds__(256, 2)
void mma_gemm(const bf16* __restrict__ A, int lda,
              const bf16* __restrict__ W, int ldw,
              float* __restrict__ C, int ldc,
              int M, int K3,
              const float* __restrict__ bias,
              const int* __restrict__ tok,
              const float* __restrict__ embP,
              const float* __restrict__ ctxP)
{
    extern __shared__ char dsm[];
    uint32_t sb = smem_u32(dsm);
    const int tid = threadIdx.x, wid = tid >> 5, lane = tid & 31;
    const int wm = wid & 1, wn = wid >> 1;        // warp tile: 64x32 at (wm*64, wn*32)
    const int m0 = blockIdx.y * 128, n0 = blockIdx.x * 128;

    float acc[4][4][4];
    #pragma unroll
    for (int i = 0; i < 4; i++)
        #pragma unroll
        for (int j = 0; j < 4; j++)
            #pragma unroll
            for (int r = 0; r < 4; r++) acc[i][j][r] = 0.f;

    const int NK = K3 / 64;
    load_tiles(sb, A, lda, W, ldw, m0, n0, 0, M, GUARD, tid);
    load_tiles(sb + STAGE_BYTES, A, lda, W, ldw, m0, n0, 64, M, GUARD, tid);

    const int a_mi = lane >> 3, a_r = lane & 7;           // x4: 4 matrices
    const int b_mi = (lane >> 3) & 1, b_r = lane & 7;     // x2: 2 matrices

    for (int j = 0; j < NK; j++) {
        asm volatile("cp.async.wait_group %0;" :: "n"(NSTAGE - 2) : "memory");
        __syncthreads();
        int nst = j + NSTAGE - 1;
        if (nst < NK)
            load_tiles(sb + (uint32_t)(nst % NSTAGE) * STAGE_BYTES,
                       A, lda, W, ldw, m0, n0, nst * 64, M, GUARD, tid);

        uint32_t abase = sb + (uint32_t)(j % NSTAGE) * STAGE_BYTES;
        uint32_t bbase = abase + 16384u;
        #pragma unroll
        for (int k16 = 0; k16 < 4; k16++) {
            uint32_t af[4][4];
            #pragma unroll
            for (int mt = 0; mt < 4; mt++) {
                int row = wm * 64 + mt * 16 + ((a_mi & 1) << 3) + a_r;
                int c16 = (k16 << 1) + (a_mi >> 1);
                ldsm4(af[mt], abase + (uint32_t)(row * 128) + (uint32_t)((c16 ^ (row & 7)) << 4));
            }
            uint32_t bf[4][2];
            #pragma unroll
            for (int nt = 0; nt < 4; nt++) {
                int row = wn * 32 + nt * 8 + b_r;
                int c16 = (k16 << 1) + b_mi;
                ldsm2(bf[nt], bbase + (uint32_t)(row * 128) + (uint32_t)((c16 ^ (row & 7)) << 4));
            }
            #pragma unroll
            for (int mt = 0; mt < 4; mt++)
                #pragma unroll
                for (int nt = 0; nt < 4; nt++)
                    mma16(acc[mt][nt], af[mt], bf[nt]);
        }
    }

    #pragma unroll
    for (int mt = 0; mt < 4; mt++) {
        #pragma unroll
        for (int half = 0; half < 2; half++) {
            int row = m0 + wm * 64 + mt * 16 + (lane >> 2) + half * 8;
            if (GUARD && row >= M) continue;
            const float* ep = nullptr; const float* cq = nullptr;
            if (EPI == 1) {
                ep = embP + (size_t)tok[row] * Hn;
                cq = ctxP + (size_t)(row >> 8) * Hn;
            }
            #pragma unroll
            for (int nt = 0; nt < 4; nt++) {
                int col = n0 + wn * 32 + nt * 8 + (lane & 3) * 2;
                float vx = acc[mt][nt][half * 2];
                float vy = acc[mt][nt][half * 2 + 1];
                if (EPI == 1) {
                    vx += ep[col] + cq[col];
                    vy += ep[col + 1] + cq[col + 1];
                }
                if (EPI == 2) {
                    vx = tanhf(vx + bias[col]);
                    vy = tanhf(vy + bias[col + 1]);
                }
                *reinterpret_cast<float2*>(C + (size_t)row * ldc + col) = make_float2(vx, vy);
            }
        }
    }
}

// ================= fp32 -> split-bf16 (K'=3K) conversion =================
// PAT 0 (A side): per k emit [hi, lo, hi];  PAT 1 (B side): [hi, hi, lo]
template<int PAT>
__global__ void cvt3_kernel(const float* __restrict__ src, int lds,
                            bf16* __restrict__ dst, int K)
{
    int row = blockIdx.x;
    const float* s = src + (size_t)row * lds;
    bf162* d = reinterpret_cast<bf162*>(dst + (size_t)row * 3 * K);
    for (int k4 = threadIdx.x; k4 < K / 4; k4 += blockDim.x) {
        float4 v = *reinterpret_cast<const float4*>(s + k4 * 4);
        float a[4] = {v.x, v.y, v.z, v.w};
        bf16 h[4], l[4];
        #pragma unroll
        for (int i = 0; i < 4; i++) {
            h[i] = __float2bfloat16(a[i]);
            l[i] = __float2bfloat16(a[i] - __bfloat162float(h[i]));
        }
        bf162 o[6];
        if (PAT == 0) {
            o[0].x = h[0]; o[0].y = l[0];
            o[1].x = h[0]; o[1].y = h[1];
            o[2].x = l[1]; o[2].y = h[1];
            o[3].x = h[2]; o[3].y = l[2];
            o[4].x = h[2]; o[4].y = h[3];
            o[5].x = l[3]; o[5].y = h[3];
        } else {
            o[0].x = h[0]; o[0].y = h[0];
            o[1].x = l[0]; o[1].y = h[1];
            o[2].x = h[1]; o[2].y = l[1];
            o[3].x = h[2]; o[3].y = h[2];
            o[4].x = l[2]; o[4].y = h[3];
            o[5].x = h[3]; o[5].y = l[3];
        }
        #pragma unroll
        for (int i = 0; i < 6; i++) d[k4 * 6 + i] = o[i];
    }
}

// ================= small elementwise kernels =================
__global__ void pack_wcat(const float* __restrict__ W_ih, const float* __restrict__ W_hh) {
    int n = blockIdx.x, t = threadIdx.x;
    float* dst = g_wcat + (size_t)n * 1536;
    const float* wi = W_ih + (size_t)n * (En + H2) + En;
    for (int k = t; k < H2; k += 256) dst[k] = wi[k];
    const float* wh = W_hh + (size_t)n * Hn;
    for (int k = t; k < Hn; k += 256) dst[H2 + k] = wh[k];
}
__global__ void pack_xcat() {
    int b = blockIdx.x, t = threadIdx.x;
    float* dst = g_xcat + (size_t)b * 1536;
    for (int k = t; k < H2; k += 256) dst[k] = g_context[(size_t)b * H2 + k];
    for (int k = t; k < Hn; k += 256) dst[H2 + k] = g_h0[(size_t)b * Hn + k];
}

__global__ void scores_kernel(const float* __restrict__ eW, const int* __restrict__ srcpos) {
    int warp = threadIdx.x >> 5, lane = threadIdx.x & 31;
    int row = blockIdx.x * 8 + warp;
    int b = row >> 8;
    const float* pk = g_big + (size_t)row * Hn;
    const float* q = g_qproj + (size_t)b * Hn;
    float s = 0.f;
    for (int h = lane; h < Hn; h += 32) s += tanhf(pk[h] + q[h]) * eW[h];
    s = warp_red(s);
    if (lane == 0) g_scores[row] = (srcpos[row] != 0) ? s : -1e9f;
}

__global__ void softmax_kernel() {
    __shared__ float sm[8];
    int b = blockIdx.x, t = threadIdx.x, w = t >> 5, l = t & 31;
    float v = g_scores[b * Sn + t];
    float m = v;
    #pragma unroll
    for (int o = 16; o; o >>= 1) m = fmaxf(m, __shfl_xor_sync(0xffffffffu, m, o));
    if (l == 0) sm[w] = m;
    __syncthreads();
    m = sm[0];
    #pragma unroll
    for (int i = 1; i < 8; i++) m = fmaxf(m, sm[i]);
    __syncthreads();
    float e = expf(v - m);
    float s = e;
    #pragma unroll
    for (int o = 16; o; o >>= 1) s += __shfl_xor_sync(0xffffffffu, s, o);
    if (l == 0) sm[w] = s;
    __syncthreads();
    s = 0.f;
    #pragma unroll
    for (int i = 0; i < 8; i++) s += sm[i];
    g_scores[b * Sn + t] = e / s;
}

__global__ void context_kernel(const float* __restrict__ enc) {
    __shared__ float a[Sn];
    int b = blockIdx.x;
    int d = blockIdx.y * 256 + threadIdx.x;
    a[threadIdx.x] = g_scores[b * Sn + threadIdx.x];
    __syncthreads();
    const float* e = enc + (size_t)b * Sn * H2 + d;
    float s = 0.f;
    #pragma unroll 4
    for (int sS = 0; sS < Sn; sS++) s += a[sS] * e[(size_t)sS * H2];
    g_context[(size_t)b * H2 + d] = s;
}

// LSTM cell -> h, emitted directly as split-bf16 A-pattern rows (K=512 -> 1536)
__global__ void gates_kernel(const int* __restrict__ tgt,
                             const float* __restrict__ b_ih,
                             const float* __restrict__ b_hh) {
    int row = blockIdx.x;
    int t = threadIdx.x;
    int b = row >> 8;
    int tok = tgt[row];
    const float* ew = g_embW + (size_t)tok * H4;
    const float* gc = g_gconst + (size_t)b * H4;
    float i_ = ew[t]          + gc[t]          + b_ih[t]          + b_hh[t];
    float f_ = ew[t + Hn]     + gc[t + Hn]     + b_ih[t + Hn]     + b_hh[t + Hn];
    float gg = ew[t + 2 * Hn] + gc[t + 2 * Hn] + b_ih[t + 2 * Hn] + b_hh[t + 2 * Hn];
    float o_ = ew[t + 3 * Hn] + gc[t + 3 * Hn] + b_ih[t + 3 * Hn] + b_hh[t + 3 * Hn];
    float c = sigf(f_) * g_c0[(size_t)b * Hn + t] + sigf(i_) * tanhf(gg);
    float h = sigf(o_) * tanhf(c);
    bf16 hi = __float2bfloat16(h);
    bf16 lo = __float2bfloat16(h - __bfloat162float(hi));
    bf16* d = g_h3 + (size_t)row * 1536 + 3 * t;
    d[0] = hi; d[1] = lo; d[2] = hi;
}

// =========================================================================================
extern "C" void kernel_launch(void* const* d_in, const int* in_sizes, int n_in,
                              void* d_out, int out_size)
{
    const int*   tgt     = (const int*)  d_in[0];
    const float* enc     = (const float*)d_in[1];
    const float* eh      = (const float*)d_in[2];
    const float* ec      = (const float*)d_in[3];
    const int*   srcpos  = (const int*)  d_in[4];
    const float* emb     = (const float*)d_in[5];
    const float* key_W   = (const float*)d_in[6];
    const float* query_W = (const float*)d_in[7];
    const float* eW      = (const float*)d_in[8];
    const float* W_ih    = (const float*)d_in[9];
    const float* W_hh    = (const float*)d_in[10];
    const float* b_ih    = (const float*)d_in[11];
    const float* b_hh    = (const float*)d_in[12];
    const float* bhW     = (const float*)d_in[13];
    const float* bhb     = (const float*)d_in[14];
    const float* bcW     = (const float*)d_in[15];
    const float* bcb     = (const float*)d_in[16];
    const float* pre_W   = (const float*)d_in[17];
    float* out = (float*)d_out;

    float *p_h0, *p_c0, *p_qproj, *p_context, *p_ctxP, *p_embW, *p_embP, *p_big, *p_xcat, *p_wcat, *p_gconst;
    cudaGetSymbolAddress((void**)&p_h0, g_h0);
    cudaGetSymbolAddress((void**)&p_c0, g_c0);
    cudaGetSymbolAddress((void**)&p_qproj, g_qproj);
    cudaGetSymbolAddress((void**)&p_context, g_context);
    cudaGetSymbolAddress((void**)&p_ctxP, g_ctxP);
    cudaGetSymbolAddress((void**)&p_embW, g_embW);
    cudaGetSymbolAddress((void**)&p_embP, g_embP);
    cudaGetSymbolAddress((void**)&p_big, g_big);
    cudaGetSymbolAddress((void**)&p_xcat, g_xcat);
    cudaGetSymbolAddress((void**)&p_wcat, g_wcat);
    cudaGetSymbolAddress((void**)&p_gconst, g_gconst);

    bf16 *p_emb3, *p_Wih3, *p_preWe3, *p_key3, *p_enc3, *p_bhW3, *p_bcW3, *p_qW3;
    bf16 *p_eh3, *p_ec3, *p_h03, *p_ctx3, *p_xcat3, *p_wcat3, *p_preWh3, *p_preWc3, *p_h3;
    cudaGetSymbolAddress((void**)&p_emb3, g_emb3);
    cudaGetSymbolAddress((void**)&p_Wih3, g_Wih3);
    cudaGetSymbolAddress((void**)&p_preWe3, g_preWe3);
    cudaGetSymbolAddress((void**)&p_key3, g_key3);
    cudaGetSymbolAddress((void**)&p_enc3, g_enc3);
    cudaGetSymbolAddress((void**)&p_bhW3, g_bhW3);
    cudaGetSymbolAddress((void**)&p_bcW3, g_bcW3);
    cudaGetSymbolAddress((void**)&p_qW3, g_qW3);
    cudaGetSymbolAddress((void**)&p_eh3, g_eh3);
    cudaGetSymbolAddress((void**)&p_ec3, g_ec3);
    cudaGetSymbolAddress((void**)&p_h03, g_h03);
    cudaGetSymbolAddress((void**)&p_ctx3, g_ctx3);
    cudaGetSymbolAddress((void**)&p_xcat3, g_xcat3);
    cudaGetSymbolAddress((void**)&p_wcat3, g_wcat3);
    cudaGetSymbolAddress((void**)&p_preWh3, g_preWh3);
    cudaGetSymbolAddress((void**)&p_preWc3, g_preWc3);
    cudaGetSymbolAddress((void**)&p_h3, g_h3);

    cudaFuncSetAttribute(mma_gemm<false, 0>, cudaFuncAttributeMaxDynamicSharedMemorySize, SMEM_DYN);
    cudaFuncSetAttribute(mma_gemm<false, 1>, cudaFuncAttributeMaxDynamicSharedMemorySize, SMEM_DYN);
    cudaFuncSetAttribute(mma_gemm<false, 2>, cudaFuncAttributeMaxDynamicSharedMemorySize, SMEM_DYN);
    cudaFuncSetAttribute(mma_gemm<true, 0>,  cudaFuncAttributeMaxDynamicSharedMemorySize, SMEM_DYN);

    // ---- conversions of inputs to split-bf16 (K' = 3K) ----
    cvt3_kernel<0><<<Vn, 128>>>(emb, En, p_emb3, En);
    cvt3_kernel<1><<<H4, 128>>>(W_ih, En + H2, p_Wih3, En);
    cvt3_kernel<1><<<Hn, 128>>>(pre_W, En + Hn + H2, p_preWe3, En);
    cvt3_kernel<1><<<Hn, 128>>>(key_W, H2, p_key3, H2);
    cvt3_kernel<0><<<Bn * Sn, 128>>>(enc, H2, p_enc3, H2);
    cvt3_kernel<1><<<Hn, 128>>>(bhW, H2, p_bhW3, H2);
    cvt3_kernel<1><<<Hn, 128>>>(bcW, H2, p_bcW3, H2);
    cvt3_kernel<1><<<Hn, 128>>>(query_W, Hn, p_qW3, Hn);
    cvt3_kernel<0><<<Bn, 128>>>(eh, H2, p_eh3, H2);
    cvt3_kernel<0><<<Bn, 128>>>(ec, H2, p_ec3, H2);
    cvt3_kernel<1><<<Hn, 128>>>(pre_W + En, En + Hn + H2, p_preWh3, Hn);
    cvt3_kernel<1><<<Hn, 128>>>(pre_W + En + Hn, En + Hn + H2, p_preWc3, H2);
    pack_wcat<<<H4, 256>>>(W_ih, W_hh);
    cvt3_kernel<1><<<H4, 128>>>(p_wcat, 1536, p_wcat3, 1536);

    // ---- vocab-level precomputes ----
    mma_gemm<true, 0><<<dim3(H4 / 128, (Vn + 127) / 128), 256, SMEM_DYN>>>(
        p_emb3, 768, p_Wih3, 768, p_embW, H4, Vn, 768, nullptr, nullptr, nullptr, nullptr);
    mma_gemm<true, 0><<<dim3(Hn / 128, (Vn + 127) / 128), 256, SMEM_DYN>>>(
        p_emb3, 768, p_preWe3, 768, p_embP, Hn, Vn, 768, nullptr, nullptr, nullptr, nullptr);

    // ---- bridges: h0/c0 = tanh(x @ W.T + b) ----
    mma_gemm<false, 2><<<dim3(Hn / 128, 1), 256, SMEM_DYN>>>(
        p_eh3, 3072, p_bhW3, 3072, p_h0, Hn, Bn, 3072, bhb, nullptr, nullptr, nullptr);
    mma_gemm<false, 2><<<dim3(Hn / 128, 1), 256, SMEM_DYN>>>(
        p_ec3, 3072, p_bcW3, 3072, p_c0, Hn, Bn, 3072, bcb, nullptr, nullptr, nullptr);
    cvt3_kernel<0><<<Bn, 128>>>(p_h0, Hn, p_h03, Hn);
    // qproj = h0 @ query_W.T
    mma_gemm<false, 0><<<dim3(Hn / 128, 1), 256, SMEM_DYN>>>(
        p_h03, 1536, p_qW3, 1536, p_qproj, Hn, Bn, 1536, nullptr, nullptr, nullptr, nullptr);
    // PK = enc2d @ key_W.T -> g_big
    mma_gemm<false, 0><<<dim3(Hn / 128, (Bn * Sn) / 128), 256, SMEM_DYN>>>(
        p_enc3, 3072, p_key3, 3072, p_big, Hn, Bn * Sn, 3072, nullptr, nullptr, nullptr, nullptr);
    // attention
    scores_kernel<<<(Bn * Sn) / 8, 256>>>(eW, srcpos);
    softmax_kernel<<<Bn, Sn>>>();
    context_kernel<<<dim3(Bn, H2 / 256), 256>>>(enc);
    // gconst = [ctx|h0] @ [W_ih[:,E:] | W_hh].T
    pack_xcat<<<Bn, 256>>>();
    cvt3_kernel<0><<<Bn, 128>>>(p_xcat, 1536, p_xcat3, 1536);
    mma_gemm<false, 0><<<dim3(H4 / 128, 1), 256, SMEM_DYN>>>(
        p_xcat3, 4608, p_wcat3, 4608, p_gconst, H4, Bn, 4608, nullptr, nullptr, nullptr, nullptr);
    // ctxP = ctx @ pre_W[:, E+H:].T
    cvt3_kernel<0><<<Bn, 128>>>(p_context, H2, p_ctx3, H2);
    mma_gemm<false, 0><<<dim3(Hn / 128, 1), 256, SMEM_DYN>>>(
        p_ctx3, 3072, p_preWc3, 3072, p_ctxP, Hn, Bn, 3072, nullptr, nullptr, nullptr, nullptr);
    // LSTM cell -> h3 (split-bf16)
    gates_kernel<<<Bn * Tn, Hn>>>(tgt, b_ih, b_hh);
    // out = h @ pre_W[:, E:E+H].T + embP[tok] + ctxP[b]
    mma_gemm<false, 1><<<dim3(Hn / 128, (Bn * Tn) / 128), 256, SMEM_DYN>>>(
        p_h3, 1536, p_preWh3, 1536, out, Hn, Bn * Tn, 1536, nullptr, tgt, p_embP, p_ctxP);

    (void)in_sizes; (void)n_in; (void)out_size;
}

// round 5
// speedup vs baseline: 2.3560x; 1.1192x over previous
#include <cuda_runtime.h>
#include <cuda_bf16.h>
#include <math.h>
#include <stdint.h>

#define Bn 128
#define Tn 256
#define Sn 256
#define Hn 512
#define En 256
#define Vn 10000
#define H2 1024
#define H4 2048

typedef __nv_bfloat16 bf16;
typedef __nv_bfloat162 bf162;

// ---------------- fp32 scratch ----------------
__device__ float g_h0[Bn * Hn];
__device__ float g_c0[Bn * Hn];
__device__ float g_qproj[Bn * Hn];
__device__ float g_scores[Bn * Sn];
__device__ float g_context[Bn * H2];
__device__ float g_gconst[Bn * H4];
__device__ float g_ctxP[Bn * Hn];
__device__ float g_embW[(size_t)Vn * H4];
__device__ float g_embP[(size_t)Vn * Hn];
__device__ float g_big[(size_t)Bn * Sn * Hn];

// ---------------- split-bf16 (K'=3K) scratch ----------------
__device__ bf16 g_emb3[(size_t)Vn * 768];
__device__ bf16 g_Wih3[(size_t)H4 * 768];
__device__ bf16 g_preWe3[(size_t)Hn * 768];
__device__ bf16 g_key3[(size_t)Hn * 3072];
__device__ bf16 g_enc3[(size_t)Bn * Sn * 3072];
__device__ bf16 g_bhW3[(size_t)Hn * 3072];
__device__ bf16 g_bcW3[(size_t)Hn * 3072];
__device__ bf16 g_qW3[(size_t)Hn * 1536];
__device__ bf16 g_eh3[(size_t)Bn * 3072];
__device__ bf16 g_ec3[(size_t)Bn * 3072];
__device__ bf16 g_h03[(size_t)Bn * 1536];
__device__ bf16 g_ctx3[(size_t)Bn * 3072];
__device__ bf16 g_xcat3[(size_t)Bn * 4608];
__device__ bf16 g_wcat3[(size_t)H4 * 4608];
__device__ bf16 g_preWh3[(size_t)Hn * 1536];
__device__ bf16 g_preWc3[(size_t)Hn * 3072];
__device__ bf16 g_h3[(size_t)Bn * Tn * 1536];

__device__ __forceinline__ float sigf(float x) { return 1.f / (1.f + expf(-x)); }
__device__ __forceinline__ float warp_red(float v) {
    #pragma unroll
    for (int o = 16; o; o >>= 1) v += __shfl_down_sync(0xffffffffu, v, o);
    return v;
}

// ================= PTX helpers (portable sm_80+ subset) =================
__device__ __forceinline__ uint32_t smem_u32(const void* p) {
    uint32_t a;
    asm("{ .reg .u64 t; cvta.to.shared.u64 t, %1; cvt.u32.u64 %0, t; }" : "=r"(a) : "l"(p));
    return a;
}
__device__ __forceinline__ void cp16(uint32_t dst, const void* src) {
    asm volatile("cp.async.cg.shared.global [%0], [%1], 16;" :: "r"(dst), "l"(src) : "memory");
}
__device__ __forceinline__ void ldsm4(uint32_t* r, uint32_t addr) {
    asm volatile("ldmatrix.sync.aligned.m8n8.x4.shared.b16 {%0,%1,%2,%3}, [%4];"
                 : "=r"(r[0]), "=r"(r[1]), "=r"(r[2]), "=r"(r[3]) : "r"(addr));
}
__device__ __forceinline__ void mma16(float* c, const uint32_t* a, const uint32_t* b) {
    asm volatile("mma.sync.aligned.m16n8k16.row.col.f32.bf16.bf16.f32 "
                 "{%0,%1,%2,%3}, {%4,%5,%6,%7}, {%8,%9}, {%0,%1,%2,%3};"
                 : "+f"(c[0]), "+f"(c[1]), "+f"(c[2]), "+f"(c[3])
                 : "r"(a[0]), "r"(a[1]), "r"(a[2]), "r"(a[3]), "r"(b[0]), "r"(b[1]));
}

// ================= split-bf16 mma.sync GEMM-NT =================
#define NSTAGE 3
#define STAGE_BYTES 32768
#define SMEM_DYN (NSTAGE * STAGE_BYTES)

__device__ __forceinline__ void load_tiles(uint32_t base,
                                           const bf16* __restrict__ A, int lda,
                                           const bf16* __restrict__ W, int ldw,
                                           int m0, int n0, int k0, int M, bool guard, int tid)
{
    uint32_t ab = base, bb = base + 16384u;
    #pragma unroll
    for (int i = 0; i < 4; i++) {
        int c = tid + i * 256;
        int row = c >> 3, c16 = c & 7;
        uint32_t off = (uint32_t)(row * 128) + (uint32_t)((c16 ^ (row & 7)) << 4);
        int ar = m0 + row;
        if (guard && ar >= M) ar = M - 1;
        cp16(ab + off, A + (size_t)ar * lda + k0 + c16 * 8);
        cp16(bb + off, W + (size_t)(n0 + row) * ldw + k0 + c16 * 8);
    }
    asm volatile("cp.async.commit_group;" ::: "memory");
}

// EPI: 0 = none; 1 = +embP[tok[row]] + ctxP[row>>8]; 2 = tanh(acc + bias[col])
template<bool GUARD, int EPI>
__global__ __launch_bounds__(256, 2)
void mma_gemm(const bf16* __restrict__ A, int lda,
              const bf16* __restrict__ W, int ldw,
              float* __restrict__ C, int ldc,
              int M, int K3,
              const float* __restrict__ bias,
              const int* __restrict__ tok,
              const float* __restrict__ embP,
              const float* __restrict__ ctxP)
{
    extern __shared__ char dsm[];
    uint32_t sb = smem_u32(dsm);
    const int tid = threadIdx.x, wid = tid >> 5, lane = tid & 31;
    const int wm = wid & 1, wn = wid >> 1;        // warp tile: 64x32 at (wm*64, wn*32)
    const int m0 = blockIdx.y * 128, n0 = blockIdx.x * 128;

    float acc[4][4][4];
    #pragma unroll
    for (int i = 0; i < 4; i++)
        #pragma unroll
        for (int j = 0; j < 4; j++)
            #pragma unroll
            for (int r = 0; r < 4; r++) acc[i][j][r] = 0.f;

    const int NK = K3 / 64;
    load_tiles(sb, A, lda, W, ldw, m0, n0, 0, M, GUARD, tid);
    load_tiles(sb + STAGE_BYTES, A, lda, W, ldw, m0, n0, 64, M, GUARD, tid);

    const int a_mi = lane >> 3, a_r = lane & 7;     // A x4 addressing
    const int b_grp = lane >> 3, b_r = lane & 7;    // B x4 addressing: grp -> (nt_sel, kh)

    for (int j = 0; j < NK; j++) {
        asm volatile("cp.async.wait_group %0;" :: "n"(NSTAGE - 2) : "memory");
        __syncthreads();
        int nst = j + NSTAGE - 1;
        if (nst < NK)
            load_tiles(sb + (uint32_t)(nst % NSTAGE) * STAGE_BYTES,
                       A, lda, W, ldw, m0, n0, nst * 64, M, GUARD, tid);

        uint32_t abase = sb + (uint32_t)(j % NSTAGE) * STAGE_BYTES;
        uint32_t bbase = abase + 16384u;
        #pragma unroll
        for (int k16 = 0; k16 < 4; k16++) {
            uint32_t af[4][4];
            #pragma unroll
            for (int mt = 0; mt < 4; mt++) {
                int row = wm * 64 + mt * 16 + ((a_mi & 1) << 3) + a_r;
                int c16 = (k16 << 1) + (a_mi >> 1);
                ldsm4(af[mt], abase + (uint32_t)(row * 128) + (uint32_t)((c16 ^ (row & 7)) << 4));
            }
            // B: one ldsm4 covers two nt tiles (both k-halves each)
            uint32_t bfl[8];
            #pragma unroll
            for (int p = 0; p < 2; p++) {
                int row = wn * 32 + p * 16 + ((b_grp >> 1) << 3) + b_r;
                int c16 = (k16 << 1) + (b_grp & 1);
                ldsm4(&bfl[p * 4], bbase + (uint32_t)(row * 128) + (uint32_t)((c16 ^ (row & 7)) << 4));
            }
            #pragma unroll
            for (int mt = 0; mt < 4; mt++)
                #pragma unroll
                for (int nt = 0; nt < 4; nt++)
                    mma16(acc[mt][nt], af[mt], &bfl[nt * 2]);
        }
    }

    #pragma unroll
    for (int mt = 0; mt < 4; mt++) {
        #pragma unroll
        for (int half = 0; half < 2; half++) {
            int row = m0 + wm * 64 + mt * 16 + (lane >> 2) + half * 8;
            if (GUARD && row >= M) continue;
            const float* ep = nullptr; const float* cq = nullptr;
            if (EPI == 1) {
                ep = embP + (size_t)tok[row] * Hn;
                cq = ctxP + (size_t)(row >> 8) * Hn;
            }
            #pragma unroll
            for (int nt = 0; nt < 4; nt++) {
                int col = n0 + wn * 32 + nt * 8 + (lane & 3) * 2;
                float vx = acc[mt][nt][half * 2];
                float vy = acc[mt][nt][half * 2 + 1];
                if (EPI == 1) {
                    vx += ep[col] + cq[col];
                    vy += ep[col + 1] + cq[col + 1];
                }
                if (EPI == 2) {
                    vx = tanhf(vx + bias[col]);
                    vy = tanhf(vy + bias[col + 1]);
                }
                *reinterpret_cast<float2*>(C + (size_t)row * ldc + col) = make_float2(vx, vy);
            }
        }
    }
}

// ================= fp32 -> split-bf16 (K'=3K) conversion =================
// PAT 0 (A side): per k emit [hi, lo, hi];  PAT 1 (B side): [hi, hi, lo]
template<int PAT>
__global__ void cvt3_kernel(const float* __restrict__ src, int lds,
                            bf16* __restrict__ dst, int K)
{
    int row = blockIdx.x;
    const float* s = src + (size_t)row * lds;
    uint2* d = reinterpret_cast<uint2*>(dst + (size_t)row * 3 * K);
    for (int k4 = threadIdx.x; k4 < K / 4; k4 += blockDim.x) {
        float4 v = *reinterpret_cast<const float4*>(s + k4 * 4);
        float a[4] = {v.x, v.y, v.z, v.w};
        bf16 h[4], l[4];
        #pragma unroll
        for (int i = 0; i < 4; i++) {
            h[i] = __float2bfloat16(a[i]);
            l[i] = __float2bfloat16(a[i] - __bfloat162float(h[i]));
        }
        bf16 o[12];
        if (PAT == 0) {
            o[0] = h[0]; o[1]  = l[0]; o[2]  = h[0];
            o[3] = h[1]; o[4]  = l[1]; o[5]  = h[1];
            o[6] = h[2]; o[7]  = l[2]; o[8]  = h[2];
            o[9] = h[3]; o[10] = l[3]; o[11] = h[3];
        } else {
            o[0] = h[0]; o[1]  = h[0]; o[2]  = l[0];
            o[3] = h[1]; o[4]  = h[1]; o[5]  = l[1];
            o[6] = h[2]; o[7]  = h[2]; o[8]  = l[2];
            o[9] = h[3]; o[10] = h[3]; o[11] = l[3];
        }
        const uint2* ou = reinterpret_cast<const uint2*>(o);
        d[k4 * 3 + 0] = ou[0];
        d[k4 * 3 + 1] = ou[1];
        d[k4 * 3 + 2] = ou[2];
    }
}

// ================= fused pack + split kernels =================
// wcat3[n, :] = split-B of [W_ih[n, E:] | W_hh[n, :]]   (K = 1536 -> 4608)
__global__ void pack_wcat3(const float* __restrict__ W_ih, const float* __restrict__ W_hh) {
    int n = blockIdx.x;
    bf16* d = g_wcat3 + (size_t)n * 4608;
    const float* wi = W_ih + (size_t)n * (En + H2) + En;
    const float* wh = W_hh + (size_t)n * Hn;
    for (int k = threadIdx.x; k < 1536; k += blockDim.x) {
        float a = (k < H2) ? wi[k] : wh[k - H2];
        bf16 hi = __float2bfloat16(a);
        bf16 lo = __float2bfloat16(a - __bfloat162float(hi));
        d[3 * k] = hi; d[3 * k + 1] = hi; d[3 * k + 2] = lo;
    }
}
// xcat3[b, :] = split-A of [context[b,:] | h0[b,:]]
__global__ void pack_xcat3() {
    int b = blockIdx.x;
    bf16* d = g_xcat3 + (size_t)b * 4608;
    for (int k = threadIdx.x; k < 1536; k += blockDim.x) {
        float a = (k < H2) ? g_context[(size_t)b * H2 + k] : g_h0[(size_t)b * Hn + (k - H2)];
        bf16 hi = __float2bfloat16(a);
        bf16 lo = __float2bfloat16(a - __bfloat162float(hi));
        d[3 * k] = hi; d[3 * k + 1] = lo; d[3 * k + 2] = hi;
    }
}

// ================= small elementwise kernels =================
__global__ void scores_kernel(const float* __restrict__ eW, const int* __restrict__ srcpos) {
    int warp = threadIdx.x >> 5, lane = threadIdx.x & 31;
    int row = blockIdx.x * 8 + warp;
    int b = row >> 8;
    const float* pk = g_big + (size_t)row * Hn;
    const float* q = g_qproj + (size_t)b * Hn;
    float s = 0.f;
    for (int h = lane; h < Hn; h += 32) s += tanhf(pk[h] + q[h]) * eW[h];
    s = warp_red(s);
    if (lane == 0) g_scores[row] = (srcpos[row] != 0) ? s : -1e9f;
}

__global__ void softmax_kernel() {
    __shared__ float sm[8];
    int b = blockIdx.x, t = threadIdx.x, w = t >> 5, l = t & 31;
    float v = g_scores[b * Sn + t];
    float m = v;
    #pragma unroll
    for (int o = 16; o; o >>= 1) m = fmaxf(m, __shfl_xor_sync(0xffffffffu, m, o));
    if (l == 0) sm[w] = m;
    __syncthreads();
    m = sm[0];
    #pragma unroll
    for (int i = 1; i < 8; i++) m = fmaxf(m, sm[i]);
    __syncthreads();
    float e = expf(v - m);
    float s = e;
    #pragma unroll
    for (int o = 16; o; o >>= 1) s += __shfl_xor_sync(0xffffffffu, s, o);
    if (l == 0) sm[w] = s;
    __syncthreads();
    s = 0.f;
    #pragma unroll
    for (int i = 0; i < 8; i++) s += sm[i];
    g_scores[b * Sn + t] = e / s;
}

__global__ void context_kernel(const float* __restrict__ enc) {
    __shared__ float a[Sn];
    int b = blockIdx.x;
    int d = blockIdx.y * 256 + threadIdx.x;
    a[threadIdx.x] = g_scores[b * Sn + threadIdx.x];
    __syncthreads();
    const float* e = enc + (size_t)b * Sn * H2 + d;
    float s = 0.f;
    #pragma unroll 4
    for (int sS = 0; sS < Sn; sS++) s += a[sS] * e[(size_t)sS * H2];
    g_context[(size_t)b * H2 + d] = s;
}

// LSTM cell -> h in split-A form, staged via smem for coalesced stores
__global__ void gates_kernel(const int* __restrict__ tgt,
                             const float* __restrict__ b_ih,
                             const float* __restrict__ b_hh) {
    __shared__ bf16 sh[1536];
    int row = blockIdx.x;
    int t = threadIdx.x;
    int b = row >> 8;
    int tok = tgt[row];
    const float* ew = g_embW + (size_t)tok * H4;
    const float* gc = g_gconst + (size_t)b * H4;
    float i_ = ew[t]          + gc[t]          + b_ih[t]          + b_hh[t];
    float f_ = ew[t + Hn]     + gc[t + Hn]     + b_ih[t + Hn]     + b_hh[t + Hn];
    float gg = ew[t + 2 * Hn] + gc[t + 2 * Hn] + b_ih[t + 2 * Hn] + b_hh[t + 2 * Hn];
    float o_ = ew[t + 3 * Hn] + gc[t + 3 * Hn] + b_ih[t + 3 * Hn] + b_hh[t + 3 * Hn];
    float c = sigf(f_) * g_c0[(size_t)b * Hn + t] + sigf(i_) * tanhf(gg);
    float h = sigf(o_) * tanhf(c);
    bf16 hi = __float2bfloat16(h);
    bf16 lo = __float2bfloat16(h - __bfloat162float(hi));
    sh[3 * t] = hi; sh[3 * t + 1] = lo; sh[3 * t + 2] = hi;
    __syncthreads();
    uint4* dst = reinterpret_cast<uint4*>(g_h3 + (size_t)row * 1536);
    const uint4* src = reinterpret_cast<const uint4*>(sh);
    if (t < 192) dst[t] = src[t];
}

// ================= stream/event setup at load time (host resources only) ===============
static cudaStream_t g_s1, g_s2;
static cudaEvent_t g_eFork, g_eS2, g_eEmbW, g_eEmbP;
namespace {
struct StreamInit {
    StreamInit() {
        cudaStreamCreateWithFlags(&g_s1, cudaStreamNonBlocking);
        cudaStreamCreateWithFlags(&g_s2, cudaStreamNonBlocking);
        cudaEventCreateWithFlags(&g_eFork, cudaEventDisableTiming);
        cudaEventCreateWithFlags(&g_eS2, cudaEventDisableTiming);
        cudaEventCreateWithFlags(&g_eEmbW, cudaEventDisableTiming);
        cudaEventCreateWithFlags(&g_eEmbP, cudaEventDisableTiming);
    }
} g_streamInit;
}

// =========================================================================================
extern "C" void kernel_launch(void* const* d_in, const int* in_sizes, int n_in,
                              void* d_out, int out_size)
{
    const int*   tgt     = (const int*)  d_in[0];
    const float* enc     = (const float*)d_in[1];
    const float* eh      = (const float*)d_in[2];
    const float* ec      = (const float*)d_in[3];
    const int*   srcpos  = (const int*)  d_in[4];
    const float* emb     = (const float*)d_in[5];
    const float* key_W   = (const float*)d_in[6];
    const float* query_W = (const float*)d_in[7];
    const float* eW      = (const float*)d_in[8];
    const float* W_ih    = (const float*)d_in[9];
    const float* W_hh    = (const float*)d_in[10];
    const float* b_ih    = (const float*)d_in[11];
    const float* b_hh    = (const float*)d_in[12];
    const float* bhW     = (const float*)d_in[13];
    const float* bhb     = (const float*)d_in[14];
    const float* bcW     = (const float*)d_in[15];
    const float* bcb     = (const float*)d_in[16];
    const float* pre_W   = (const float*)d_in[17];
    float* out = (float*)d_out;

    float *p_h0, *p_c0, *p_qproj, *p_context, *p_ctxP, *p_embW, *p_embP, *p_big;
    cudaGetSymbolAddress((void**)&p_h0, g_h0);
    cudaGetSymbolAddress((void**)&p_c0, g_c0);
    cudaGetSymbolAddress((void**)&p_qproj, g_qproj);
    cudaGetSymbolAddress((void**)&p_context, g_context);
    cudaGetSymbolAddress((void**)&p_ctxP, g_ctxP);
    cudaGetSymbolAddress((void**)&p_embW, g_embW);
    cudaGetSymbolAddress((void**)&p_embP, g_embP);
    cudaGetSymbolAddress((void**)&p_big, g_big);
    float* p_gconst;
    cudaGetSymbolAddress((void**)&p_gconst, g_gconst);

    bf16 *p_emb3, *p_Wih3, *p_preWe3, *p_key3, *p_enc3, *p_bhW3, *p_bcW3, *p_qW3;
    bf16 *p_eh3, *p_ec3, *p_h03, *p_ctx3, *p_xcat3, *p_wcat3, *p_preWh3, *p_preWc3, *p_h3;
    cudaGetSymbolAddress((void**)&p_emb3, g_emb3);
    cudaGetSymbolAddress((void**)&p_Wih3, g_Wih3);
    cudaGetSymbolAddress((void**)&p_preWe3, g_preWe3);
    cudaGetSymbolAddress((void**)&p_key3, g_key3);
    cudaGetSymbolAddress((void**)&p_enc3, g_enc3);
    cudaGetSymbolAddress((void**)&p_bhW3, g_bhW3);
    cudaGetSymbolAddress((void**)&p_bcW3, g_bcW3);
    cudaGetSymbolAddress((void**)&p_qW3, g_qW3);
    cudaGetSymbolAddress((void**)&p_eh3, g_eh3);
    cudaGetSymbolAddress((void**)&p_ec3, g_ec3);
    cudaGetSymbolAddress((void**)&p_h03, g_h03);
    cudaGetSymbolAddress((void**)&p_ctx3, g_ctx3);
    cudaGetSymbolAddress((void**)&p_xcat3, g_xcat3);
    cudaGetSymbolAddress((void**)&p_wcat3, g_wcat3);
    cudaGetSymbolAddress((void**)&p_preWh3, g_preWh3);
    cudaGetSymbolAddress((void**)&p_preWc3, g_preWc3);
    cudaGetSymbolAddress((void**)&p_h3, g_h3);

    cudaFuncSetAttribute(mma_gemm<false, 0>, cudaFuncAttributeMaxDynamicSharedMemorySize, SMEM_DYN);
    cudaFuncSetAttribute(mma_gemm<false, 1>, cudaFuncAttributeMaxDynamicSharedMemorySize, SMEM_DYN);
    cudaFuncSetAttribute(mma_gemm<false, 2>, cudaFuncAttributeMaxDynamicSharedMemorySize, SMEM_DYN);
    cudaFuncSetAttribute(mma_gemm<true, 0>,  cudaFuncAttributeMaxDynamicSharedMemorySize, SMEM_DYN);

    // ---- fork ----
    cudaEventRecord(g_eFork, 0);
    cudaStreamWaitEvent(g_s1, g_eFork, 0);
    cudaStreamWaitEvent(g_s2, g_eFork, 0);

    // ===== branch s1: vocab precomputes =====
    cvt3_kernel<0><<<Vn, 128, 0, g_s1>>>(emb, En, p_emb3, En);
    cvt3_kernel<1><<<H4, 128, 0, g_s1>>>(W_ih, En + H2, p_Wih3, En);
    cvt3_kernel<1><<<Hn, 128, 0, g_s1>>>(pre_W, En + Hn + H2, p_preWe3, En);
    mma_gemm<true, 0><<<dim3(H4 / 128, (Vn + 127) / 128), 256, SMEM_DYN, g_s1>>>(
        p_emb3, 768, p_Wih3, 768, p_embW, H4, Vn, 768, nullptr, nullptr, nullptr, nullptr);
    cudaEventRecord(g_eEmbW, g_s1);
    mma_gemm<true, 0><<<dim3(Hn / 128, (Vn + 127) / 128), 256, SMEM_DYN, g_s1>>>(
        p_emb3, 768, p_preWe3, 768, p_embP, Hn, Vn, 768, nullptr, nullptr, nullptr, nullptr);
    cudaEventRecord(g_eEmbP, g_s1);

    // ===== branch s2: weight cvts + bridges + qproj =====
    cvt3_kernel<1><<<Hn, 128, 0, g_s2>>>(bhW, H2, p_bhW3, H2);
    cvt3_kernel<1><<<Hn, 128, 0, g_s2>>>(bcW, H2, p_bcW3, H2);
    cvt3_kernel<1><<<Hn, 128, 0, g_s2>>>(query_W, Hn, p_qW3, Hn);
    cvt3_kernel<0><<<Bn, 128, 0, g_s2>>>(eh, H2, p_eh3, H2);
    cvt3_kernel<0><<<Bn, 128, 0, g_s2>>>(ec, H2, p_ec3, H2);
    cvt3_kernel<1><<<Hn, 128, 0, g_s2>>>(pre_W + En, En + Hn + H2, p_preWh3, Hn);
    cvt3_kernel<1><<<Hn, 128, 0, g_s2>>>(pre_W + En + Hn, En + Hn + H2, p_preWc3, H2);
    pack_wcat3<<<H4, 256, 0, g_s2>>>(W_ih, W_hh);
    mma_gemm<false, 2><<<dim3(Hn / 128, 1), 256, SMEM_DYN, g_s2>>>(
        p_eh3, 3072, p_bhW3, 3072, p_h0, Hn, Bn, 3072, bhb, nullptr, nullptr, nullptr);
    mma_gemm<false, 2><<<dim3(Hn / 128, 1), 256, SMEM_DYN, g_s2>>>(
        p_ec3, 3072, p_bcW3, 3072, p_c0, Hn, Bn, 3072, bcb, nullptr, nullptr, nullptr);
    cvt3_kernel<0><<<Bn, 128, 0, g_s2>>>(p_h0, Hn, p_h03, Hn);
    mma_gemm<false, 0><<<dim3(Hn / 128, 1), 256, SMEM_DYN, g_s2>>>(
        p_h03, 1536, p_qW3, 1536, p_qproj, Hn, Bn, 1536, nullptr, nullptr, nullptr, nullptr);
    cudaEventRecord(g_eS2, g_s2);

    // ===== main stream s0: attention critical path =====
    cvt3_kernel<0><<<Bn * Sn, 128>>>(enc, H2, p_enc3, H2);
    cvt3_kernel<1><<<Hn, 128>>>(key_W, H2, p_key3, H2);
    mma_gemm<false, 0><<<dim3(Hn / 128, (Bn * Sn) / 128), 256, SMEM_DYN>>>(
        p_enc3, 3072, p_key3, 3072, p_big, Hn, Bn * Sn, 3072, nullptr, nullptr, nullptr, nullptr);
    cudaStreamWaitEvent(0, g_eS2, 0);          // qproj, h0, c0, wcat3, preW*3 ready
    scores_kernel<<<(Bn * Sn) / 8, 256>>>(eW, srcpos);
    softmax_kernel<<<Bn, Sn>>>();
    context_kernel<<<dim3(Bn, H2 / 256), 256>>>(enc);
    pack_xcat3<<<Bn, 256>>>();
    mma_gemm<false, 0><<<dim3(H4 / 128, 1), 256, SMEM_DYN>>>(
        p_xcat3, 4608, p_wcat3, 4608, p_gconst, H4, Bn, 4608, nullptr, nullptr, nullptr, nullptr);
    cvt3_kernel<0><<<Bn, 128>>>(p_context, H2, p_ctx3, H2);
    mma_gemm<false, 0><<<dim3(Hn / 128, 1), 256, SMEM_DYN>>>(
        p_ctx3, 3072, p_preWc3, 3072, p_ctxP, Hn, Bn, 3072, nullptr, nullptr, nullptr, nullptr);
    cudaStreamWaitEvent(0, g_eEmbW, 0);        // embW ready
    gates_kernel<<<Bn * Tn, Hn>>>(tgt, b_ih, b_hh);
    cudaStreamWaitEvent(0, g_eEmbP, 0);        // embP ready (joins s1 fully)
    mma_gemm<false, 1><<<dim3(Hn / 128, (Bn * Tn) / 128), 256, SMEM_DYN>>>(
        p_h3, 1536, p_preWh3, 1536, out, Hn, Bn * Tn, 1536, nullptr, tgt, p_embP, p_ctxP);

    (void)in_sizes; (void)n_in; (void)out_size;
}

// round 6
// speedup vs baseline: 2.6206x; 1.1123x over previous
#include <cuda_runtime.h>
#include <cuda_bf16.h>
#include <math.h>
#include <stdint.h>

#define Bn 128
#define Tn 256
#define Sn 256
#define Hn 512
#define En 256
#define Vn 10000
#define H2 1024
#define H4 2048

typedef __nv_bfloat16 bf16;

// ---------------- fp32 scratch ----------------
__device__ float g_h0[Bn * Hn];
__device__ float g_c0[Bn * Hn];
__device__ float g_qproj[Bn * Hn];
__device__ float g_part[Bn * Sn * 4];     // per-col-block score partials
__device__ float g_scores[Bn * Sn];
__device__ float g_gconst[Bn * H4];
__device__ float g_ctxP[Bn * Hn];
__device__ float g_embW[(size_t)Vn * H4];
__device__ float g_embP[(size_t)Vn * Hn];

// ---------------- split-bf16 (K'=3K) scratch ----------------
__device__ bf16 g_emb3[(size_t)Vn * 768];
__device__ bf16 g_Wih3[(size_t)H4 * 768];
__device__ bf16 g_preWe3[(size_t)Hn * 768];
__device__ bf16 g_key3[(size_t)Hn * 3072];
__device__ bf16 g_enc3[(size_t)Bn * Sn * 3072];
__device__ bf16 g_bhW3[(size_t)Hn * 3072];
__device__ bf16 g_bcW3[(size_t)Hn * 3072];
__device__ bf16 g_qW3[(size_t)Hn * 1536];
__device__ bf16 g_eh3[(size_t)Bn * 3072];
__device__ bf16 g_ec3[(size_t)Bn * 3072];
__device__ bf16 g_h03[(size_t)Bn * 1536];
__device__ bf16 g_xcat3[(size_t)Bn * 4608];   // [ctx split | h0 split]
__device__ bf16 g_wcat3[(size_t)H4 * 4608];
__device__ bf16 g_preWh3[(size_t)Hn * 1536];
__device__ bf16 g_preWc3[(size_t)Hn * 3072];
__device__ bf16 g_h3[(size_t)Bn * Tn * 1536];

__device__ __forceinline__ float sigf(float x) { return 1.f / (1.f + expf(-x)); }

// ================= PTX helpers (portable sm_80+ subset) =================
__device__ __forceinline__ uint32_t smem_u32(const void* p) {
    uint32_t a;
    asm("{ .reg .u64 t; cvta.to.shared.u64 t, %1; cvt.u32.u64 %0, t; }" : "=r"(a) : "l"(p));
    return a;
}
__device__ __forceinline__ void cp16(uint32_t dst, const void* src) {
    asm volatile("cp.async.cg.shared.global [%0], [%1], 16;" :: "r"(dst), "l"(src) : "memory");
}
__device__ __forceinline__ void ldsm4(uint32_t* r, uint32_t addr) {
    asm volatile("ldmatrix.sync.aligned.m8n8.x4.shared.b16 {%0,%1,%2,%3}, [%4];"
                 : "=r"(r[0]), "=r"(r[1]), "=r"(r[2]), "=r"(r[3]) : "r"(addr));
}
__device__ __forceinline__ void mma16(float* c, const uint32_t* a, const uint32_t* b) {
    asm volatile("mma.sync.aligned.m16n8k16.row.col.f32.bf16.bf16.f32 "
                 "{%0,%1,%2,%3}, {%4,%5,%6,%7}, {%8,%9}, {%0,%1,%2,%3};"
                 : "+f"(c[0]), "+f"(c[1]), "+f"(c[2]), "+f"(c[3])
                 : "r"(a[0]), "r"(a[1]), "r"(a[2]), "r"(a[3]), "r"(b[0]), "r"(b[1]));
}

// ================= split-bf16 mma.sync GEMM-NT (128 threads, warp 64x64) =================
#define NSTAGE 3
#define STAGE_BYTES 32768
#define SMEM_DYN (NSTAGE * STAGE_BYTES)

__device__ __forceinline__ void load_tiles(uint32_t base,
                                           const bf16* __restrict__ A, int lda,
                                           const bf16* __restrict__ W, int ldw,
                                           int m0, int n0, int k0, int M, bool guard, int tid)
{
    uint32_t ab = base, bb = base + 16384u;
    #pragma unroll
    for (int i = 0; i < 8; i++) {
        int c = tid + i * 128;
        int row = c >> 3, c16 = c & 7;
        uint32_t off = (uint32_t)(row * 128) + (uint32_t)((c16 ^ (row & 7)) << 4);
        int ar = m0 + row;
        if (guard && ar >= M) ar = M - 1;
        cp16(ab + off, A + (size_t)ar * lda + k0 + c16 * 8);
        cp16(bb + off, W + (size_t)(n0 + row) * ldw + k0 + c16 * 8);
    }
    asm volatile("cp.async.commit_group;" ::: "memory");
}

// EPI: 0 none; 1 C += embP[tok[row]] + ctxP[row>>8]; 2 C = tanh(acc + bias[col]);
//      3 attention partials: C[row*4 + bx] = sum_col tanh(acc + qp[b,col])*eW[col]
//        (for EPI=3: bias = eW, embP = qproj, C = partials, ldc unused; grid.x MUST be 4)
template<bool GUARD, int EPI>
__global__ __launch_bounds__(128, 2)
void mma_gemm(const bf16* __restrict__ A, int lda,
              const bf16* __restrict__ W, int ldw,
              float* __restrict__ C, int ldc,
              int M, int K3,
              const float* __restrict__ bias,
              const int* __restrict__ tok,
              const float* __restrict__ embP,
              const float* __restrict__ ctxP)
{
    extern __shared__ char dsm[];
    uint32_t sb = smem_u32(dsm);
    const int tid = threadIdx.x, wid = tid >> 5, lane = tid & 31;
    const int wm = wid & 1, wn = wid >> 1;        // warp tile: 64x64 at (wm*64, wn*64)
    const int m0 = blockIdx.y * 128, n0 = blockIdx.x * 128;

    float acc[4][8][4];
    #pragma unroll
    for (int i = 0; i < 4; i++)
        #pragma unroll
        for (int j = 0; j < 8; j++)
            #pragma unroll
            for (int r = 0; r < 4; r++) acc[i][j][r] = 0.f;

    const int NK = K3 / 64;
    load_tiles(sb, A, lda, W, ldw, m0, n0, 0, M, GUARD, tid);
    load_tiles(sb + STAGE_BYTES, A, lda, W, ldw, m0, n0, 64, M, GUARD, tid);

    const int a_mi = lane >> 3, a_r = lane & 7;
    const int b_grp = lane >> 3, b_r = lane & 7;

    for (int j = 0; j < NK; j++) {
        asm volatile("cp.async.wait_group %0;" :: "n"(NSTAGE - 2) : "memory");
        __syncthreads();
        int nst = j + NSTAGE - 1;
        if (nst < NK)
            load_tiles(sb + (uint32_t)(nst % NSTAGE) * STAGE_BYTES,
                       A, lda, W, ldw, m0, n0, nst * 64, M, GUARD, tid);

        uint32_t abase = sb + (uint32_t)(j % NSTAGE) * STAGE_BYTES;
        uint32_t bbase = abase + 16384u;
        #pragma unroll
        for (int k16 = 0; k16 < 4; k16++) {
            uint32_t af[4][4];
            #pragma unroll
            for (int mt = 0; mt < 4; mt++) {
                int row = wm * 64 + mt * 16 + ((a_mi & 1) << 3) + a_r;
                int c16 = (k16 << 1) + (a_mi >> 1);
                ldsm4(af[mt], abase + (uint32_t)(row * 128) + (uint32_t)((c16 ^ (row & 7)) << 4));
            }
            // B: 4 ldsm4 cover 8 n-tiles (both k-halves each); frag for nt = &bfl[nt*2]
            uint32_t bfl[16];
            #pragma unroll
            for (int p = 0; p < 4; p++) {
                int row = wn * 64 + p * 16 + ((b_grp >> 1) << 3) + b_r;
                int c16 = (k16 << 1) + (b_grp & 1);
                ldsm4(&bfl[p * 4], bbase + (uint32_t)(row * 128) + (uint32_t)((c16 ^ (row & 7)) << 4));
            }
            #pragma unroll
            for (int mt = 0; mt < 4; mt++)
                #pragma unroll
                for (int nt = 0; nt < 8; nt++)
                    mma16(acc[mt][nt], af[mt], &bfl[nt * 2]);
        }
    }

    if (EPI == 3) {
        // fused attention-scores partial: per row, sum over this CTA's 128 cols
        __syncthreads();
        float* sred = reinterpret_cast<float*>(dsm);    // [128 rows][2 wn]
        #pragma unroll
        for (int mt = 0; mt < 4; mt++) {
            #pragma unroll
            for (int half = 0; half < 2; half++) {
                int rl = wm * 64 + mt * 16 + (lane >> 2) + half * 8;
                int row = m0 + rl;
                const float* q = embP + (size_t)(row >> 8) * Hn;   // qproj
                float p = 0.f;
                #pragma unroll
                for (int nt = 0; nt < 8; nt++) {
                    int col = n0 + wn * 64 + nt * 8 + (lane & 3) * 2;
                    p += tanhf(acc[mt][nt][half * 2]     + q[col])     * bias[col];
                    p += tanhf(acc[mt][nt][half * 2 + 1] + q[col + 1]) * bias[col + 1];
                }
                p += __shfl_xor_sync(0xffffffffu, p, 1);
                p += __shfl_xor_sync(0xffffffffu, p, 2);
                if ((lane & 3) == 0) sred[rl * 2 + wn] = p;
            }
        }
        __syncthreads();
        if (tid < 128)
            C[(size_t)(m0 + tid) * 4 + blockIdx.x] = sred[tid * 2] + sred[tid * 2 + 1];
        return;
    }

    #pragma unroll
    for (int mt = 0; mt < 4; mt++) {
        #pragma unroll
        for (int half = 0; half < 2; half++) {
            int row = m0 + wm * 64 + mt * 16 + (lane >> 2) + half * 8;
            if (GUARD && row >= M) continue;
            const float* ep = nullptr; const float* cq = nullptr;
            if (EPI == 1) {
                ep = embP + (size_t)tok[row] * Hn;
                cq = ctxP + (size_t)(row >> 8) * Hn;
            }
            #pragma unroll
            for (int nt = 0; nt < 8; nt++) {
                int col = n0 + wn * 64 + nt * 8 + (lane & 3) * 2;
                float vx = acc[mt][nt][half * 2];
                float vy = acc[mt][nt][half * 2 + 1];
                if (EPI == 1) {
                    vx += ep[col] + cq[col];
                    vy += ep[col + 1] + cq[col + 1];
                }
                if (EPI == 2) {
                    vx = tanhf(vx + bias[col]);
                    vy = tanhf(vy + bias[col + 1]);
                }
                *reinterpret_cast<float2*>(C + (size_t)row * ldc + col) = make_float2(vx, vy);
            }
        }
    }
}

// ================= fp32 -> split-bf16 conversion. PAT0 A:[hi,lo,hi], PAT1 B:[hi,hi,lo] ====
template<int PAT>
__global__ void cvt3_kernel(const float* __restrict__ src, int lds,
                            bf16* __restrict__ dst, int K)
{
    int row = blockIdx.x;
    const float* s = src + (size_t)row * lds;
    uint2* d = reinterpret_cast<uint2*>(dst + (size_t)row * 3 * K);
    for (int k4 = threadIdx.x; k4 < K / 4; k4 += blockDim.x) {
        float4 v = *reinterpret_cast<const float4*>(s + k4 * 4);
        float a[4] = {v.x, v.y, v.z, v.w};
        bf16 h[4], l[4];
        #pragma unroll
        for (int i = 0; i < 4; i++) {
            h[i] = __float2bfloat16(a[i]);
            l[i] = __float2bfloat16(a[i] - __bfloat162float(h[i]));
        }
        bf16 o[12];
        #pragma unroll
        for (int i = 0; i < 4; i++) {
            if (PAT == 0) { o[3*i] = h[i]; o[3*i+1] = l[i]; o[3*i+2] = h[i]; }
            else          { o[3*i] = h[i]; o[3*i+1] = h[i]; o[3*i+2] = l[i]; }
        }
        const uint2* ou = reinterpret_cast<const uint2*>(o);
        d[k4 * 3 + 0] = ou[0];
        d[k4 * 3 + 1] = ou[1];
        d[k4 * 3 + 2] = ou[2];
    }
}

// wcat3[n,:] = split-B of [W_ih[n,E:] | W_hh[n,:]]
__global__ void pack_wcat3(const float* __restrict__ W_ih, const float* __restrict__ W_hh) {
    int n = blockIdx.x;
    bf16* d = g_wcat3 + (size_t)n * 4608;
    const float* wi = W_ih + (size_t)n * (En + H2) + En;
    const float* wh = W_hh + (size_t)n * Hn;
    for (int k = threadIdx.x; k < 1536; k += blockDim.x) {
        float a = (k < H2) ? wi[k] : wh[k - H2];
        bf16 hi = __float2bfloat16(a);
        bf16 lo = __float2bfloat16(a - __bfloat162float(hi));
        d[3 * k] = hi; d[3 * k + 1] = hi; d[3 * k + 2] = lo;
    }
}
// xcat3 tail [3072:4608] = split-A of h0
__global__ void xcat_h0() {
    int b = blockIdx.x;
    bf16* d = g_xcat3 + (size_t)b * 4608 + 3072;
    for (int k = threadIdx.x; k < Hn; k += blockDim.x) {
        float a = g_h0[(size_t)b * Hn + k];
        bf16 hi = __float2bfloat16(a);
        bf16 lo = __float2bfloat16(a - __bfloat162float(hi));
        d[3 * k] = hi; d[3 * k + 1] = lo; d[3 * k + 2] = hi;
    }
}

// ================= attention small kernels =================
__global__ void softmaxP(const int* __restrict__ srcpos) {
    __shared__ float sm[8];
    int b = blockIdx.x, t = threadIdx.x, w = t >> 5, l = t & 31;
    int row = b * Sn + t;
    float4 pp = *reinterpret_cast<const float4*>(g_part + (size_t)row * 4);
    float v = (srcpos[row] != 0) ? (pp.x + pp.y + pp.z + pp.w) : -1e9f;
    float m = v;
    #pragma unroll
    for (int o = 16; o; o >>= 1) m = fmaxf(m, __shfl_xor_sync(0xffffffffu, m, o));
    if (l == 0) sm[w] = m;
    __syncthreads();
    m = sm[0];
    #pragma unroll
    for (int i = 1; i < 8; i++) m = fmaxf(m, sm[i]);
    __syncthreads();
    float e = expf(v - m);
    float s = e;
    #pragma unroll
    for (int o = 16; o; o >>= 1) s += __shfl_xor_sync(0xffffffffu, s, o);
    if (l == 0) sm[w] = s;
    __syncthreads();
    s = 0.f;
    #pragma unroll
    for (int i = 0; i < 8; i++) s += sm[i];
    g_scores[row] = e / s;
}

// context -> directly into xcat3[0:3072] in split-A form
__global__ void context_kernel(const float* __restrict__ enc) {
    __shared__ float a[Sn];
    int b = blockIdx.x;
    int d = blockIdx.y * 256 + threadIdx.x;
    a[threadIdx.x] = g_scores[b * Sn + threadIdx.x];
    __syncthreads();
    const float* e = enc + (size_t)b * Sn * H2 + d;
    float s = 0.f;
    #pragma unroll 4
    for (int sS = 0; sS < Sn; sS++) s += a[sS] * e[(size_t)sS * H2];
    bf16 hi = __float2bfloat16(s);
    bf16 lo = __float2bfloat16(s - __bfloat162float(hi));
    bf16* dd = g_xcat3 + (size_t)b * 4608 + 3 * d;
    dd[0] = hi; dd[1] = lo; dd[2] = hi;
}

// LSTM cell -> h in split-A form
__global__ void gates_kernel(const int* __restrict__ tgt,
                             const float* __restrict__ b_ih,
                             const float* __restrict__ b_hh) {
    __shared__ bf16 sh[1536];
    int row = blockIdx.x;
    int t = threadIdx.x;
    int b = row >> 8;
    int tok = tgt[row];
    const float* ew = g_embW + (size_t)tok * H4;
    const float* gc = g_gconst + (size_t)b * H4;
    float i_ = ew[t]          + gc[t]          + b_ih[t]          + b_hh[t];
    float f_ = ew[t + Hn]     + gc[t + Hn]     + b_ih[t + Hn]     + b_hh[t + Hn];
    float gg = ew[t + 2 * Hn] + gc[t + 2 * Hn] + b_ih[t + 2 * Hn] + b_hh[t + 2 * Hn];
    float o_ = ew[t + 3 * Hn] + gc[t + 3 * Hn] + b_ih[t + 3 * Hn] + b_hh[t + 3 * Hn];
    float c = sigf(f_) * g_c0[(size_t)b * Hn + t] + sigf(i_) * tanhf(gg);
    float h = sigf(o_) * tanhf(c);
    bf16 hi = __float2bfloat16(h);
    bf16 lo = __float2bfloat16(h - __bfloat162float(hi));
    sh[3 * t] = hi; sh[3 * t + 1] = lo; sh[3 * t + 2] = hi;
    __syncthreads();
    uint4* dst = reinterpret_cast<uint4*>(g_h3 + (size_t)row * 1536);
    const uint4* src = reinterpret_cast<const uint4*>(sh);
    if (t < 192) dst[t] = src[t];
}

// ================= stream/event setup (host resources only) =================
static cudaStream_t g_s1, g_s2;
static cudaEvent_t g_eFork, g_eS2, g_eQ, g_eEmbW, g_eEmbP;
namespace {
struct StreamInit {
    StreamInit() {
        cudaStreamCreateWithFlags(&g_s1, cudaStreamNonBlocking);
        cudaStreamCreateWithFlags(&g_s2, cudaStreamNonBlocking);
        cudaEventCreateWithFlags(&g_eFork, cudaEventDisableTiming);
        cudaEventCreateWithFlags(&g_eS2, cudaEventDisableTiming);
        cudaEventCreateWithFlags(&g_eQ, cudaEventDisableTiming);
        cudaEventCreateWithFlags(&g_eEmbW, cudaEventDisableTiming);
        cudaEventCreateWithFlags(&g_eEmbP, cudaEventDisableTiming);
    }
} g_streamInit;
}

// =========================================================================================
extern "C" void kernel_launch(void* const* d_in, const int* in_sizes, int n_in,
                              void* d_out, int out_size)
{
    const int*   tgt     = (const int*)  d_in[0];
    const float* enc     = (const float*)d_in[1];
    const float* eh      = (const float*)d_in[2];
    const float* ec      = (const float*)d_in[3];
    const int*   srcpos  = (const int*)  d_in[4];
    const float* emb     = (const float*)d_in[5];
    const float* key_W   = (const float*)d_in[6];
    const float* query_W = (const float*)d_in[7];
    const float* eW      = (const float*)d_in[8];
    const float* W_ih    = (const float*)d_in[9];
    const float* W_hh    = (const float*)d_in[10];
    const float* b_ih    = (const float*)d_in[11];
    const float* b_hh    = (const float*)d_in[12];
    const float* bhW     = (const float*)d_in[13];
    const float* bhb     = (const float*)d_in[14];
    const float* bcW     = (const float*)d_in[15];
    const float* bcb     = (const float*)d_in[16];
    const float* pre_W   = (const float*)d_in[17];
    float* out = (float*)d_out;

    float *p_h0, *p_c0, *p_qproj, *p_part, *p_ctxP, *p_embW, *p_embP, *p_gconst;
    cudaGetSymbolAddress((void**)&p_h0, g_h0);
    cudaGetSymbolAddress((void**)&p_c0, g_c0);
    cudaGetSymbolAddress((void**)&p_qproj, g_qproj);
    cudaGetSymbolAddress((void**)&p_part, g_part);
    cudaGetSymbolAddress((void**)&p_ctxP, g_ctxP);
    cudaGetSymbolAddress((void**)&p_embW, g_embW);
    cudaGetSymbolAddress((void**)&p_embP, g_embP);
    cudaGetSymbolAddress((void**)&p_gconst, g_gconst);

    bf16 *p_emb3, *p_Wih3, *p_preWe3, *p_key3, *p_enc3, *p_bhW3, *p_bcW3, *p_qW3;
    bf16 *p_eh3, *p_ec3, *p_h03, *p_xcat3, *p_wcat3, *p_preWh3, *p_preWc3, *p_h3;
    cudaGetSymbolAddress((void**)&p_emb3, g_emb3);
    cudaGetSymbolAddress((void**)&p_Wih3, g_Wih3);
    cudaGetSymbolAddress((void**)&p_preWe3, g_preWe3);
    cudaGetSymbolAddress((void**)&p_key3, g_key3);
    cudaGetSymbolAddress((void**)&p_enc3, g_enc3);
    cudaGetSymbolAddress((void**)&p_bhW3, g_bhW3);
    cudaGetSymbolAddress((void**)&p_bcW3, g_bcW3);
    cudaGetSymbolAddress((void**)&p_qW3, g_qW3);
    cudaGetSymbolAddress((void**)&p_eh3, g_eh3);
    cudaGetSymbolAddress((void**)&p_ec3, g_ec3);
    cudaGetSymbolAddress((void**)&p_h03, g_h03);
    cudaGetSymbolAddress((void**)&p_xcat3, g_xcat3);
    cudaGetSymbolAddress((void**)&p_wcat3, g_wcat3);
    cudaGetSymbolAddress((void**)&p_preWh3, g_preWh3);
    cudaGetSymbolAddress((void**)&p_preWc3, g_preWc3);
    cudaGetSymbolAddress((void**)&p_h3, g_h3);

    cudaFuncSetAttribute(mma_gemm<false, 0>, cudaFuncAttributeMaxDynamicSharedMemorySize, SMEM_DYN);
    cudaFuncSetAttribute(mma_gemm<false, 1>, cudaFuncAttributeMaxDynamicSharedMemorySize, SMEM_DYN);
    cudaFuncSetAttribute(mma_gemm<false, 2>, cudaFuncAttributeMaxDynamicSharedMemorySize, SMEM_DYN);
    cudaFuncSetAttribute(mma_gemm<false, 3>, cudaFuncAttributeMaxDynamicSharedMemorySize, SMEM_DYN);
    cudaFuncSetAttribute(mma_gemm<true, 0>,  cudaFuncAttributeMaxDynamicSharedMemorySize, SMEM_DYN);

    // ---- fork ----
    cudaEventRecord(g_eFork, 0);
    cudaStreamWaitEvent(g_s1, g_eFork, 0);
    cudaStreamWaitEvent(g_s2, g_eFork, 0);

    // ===== branch s1: vocab precomputes =====
    cvt3_kernel<0><<<Vn, 128, 0, g_s1>>>(emb, En, p_emb3, En);
    cvt3_kernel<1><<<H4, 128, 0, g_s1>>>(W_ih, En + H2, p_Wih3, En);
    cvt3_kernel<1><<<Hn, 128, 0, g_s1>>>(pre_W, En + Hn + H2, p_preWe3, En);
    mma_gemm<true, 0><<<dim3(H4 / 128, (Vn + 127) / 128), 128, SMEM_DYN, g_s1>>>(
        p_emb3, 768, p_Wih3, 768, p_embW, H4, Vn, 768, nullptr, nullptr, nullptr, nullptr);
    cudaEventRecord(g_eEmbW, g_s1);
    mma_gemm<true, 0><<<dim3(Hn / 128, (Vn + 127) / 128), 128, SMEM_DYN, g_s1>>>(
        p_emb3, 768, p_preWe3, 768, p_embP, Hn, Vn, 768, nullptr, nullptr, nullptr, nullptr);
    cudaEventRecord(g_eEmbP, g_s1);

    // ===== branch s2: qproj chain first (PK epilogue needs it), then the rest =====
    cvt3_kernel<1><<<Hn, 128, 0, g_s2>>>(bhW, H2, p_bhW3, H2);
    cvt3_kernel<0><<<Bn, 128, 0, g_s2>>>(eh, H2, p_eh3, H2);
    cvt3_kernel<1><<<Hn, 128, 0, g_s2>>>(query_W, Hn, p_qW3, Hn);
    mma_gemm<false, 2><<<dim3(Hn / 128, 1), 128, SMEM_DYN, g_s2>>>(
        p_eh3, 3072, p_bhW3, 3072, p_h0, Hn, Bn, 3072, bhb, nullptr, nullptr, nullptr);
    cvt3_kernel<0><<<Bn, 128, 0, g_s2>>>(p_h0, Hn, p_h03, Hn);
    mma_gemm<false, 0><<<dim3(Hn / 128, 1), 128, SMEM_DYN, g_s2>>>(
        p_h03, 1536, p_qW3, 1536, p_qproj, Hn, Bn, 1536, nullptr, nullptr, nullptr, nullptr);
    cudaEventRecord(g_eQ, g_s2);
    xcat_h0<<<Bn, 256, 0, g_s2>>>();
    cvt3_kernel<1><<<Hn, 128, 0, g_s2>>>(bcW, H2, p_bcW3, H2);
    cvt3_kernel<0><<<Bn, 128, 0, g_s2>>>(ec, H2, p_ec3, H2);
    mma_gemm<false, 2><<<dim3(Hn / 128, 1), 128, SMEM_DYN, g_s2>>>(
        p_ec3, 3072, p_bcW3, 3072, p_c0, Hn, Bn, 3072, bcb, nullptr, nullptr, nullptr);
    pack_wcat3<<<H4, 256, 0, g_s2>>>(W_ih, W_hh);
    cvt3_kernel<1><<<Hn, 128, 0, g_s2>>>(pre_W + En, En + Hn + H2, p_preWh3, Hn);
    cvt3_kernel<1><<<Hn, 128, 0, g_s2>>>(pre_W + En + Hn, En + Hn + H2, p_preWc3, H2);
    cudaEventRecord(g_eS2, g_s2);

    // ===== main stream s0: attention critical path =====
    cvt3_kernel<1><<<Hn, 128>>>(key_W, H2, p_key3, H2);
    cvt3_kernel<0><<<Bn * Sn, 128>>>(enc, H2, p_enc3, H2);
    cudaStreamWaitEvent(0, g_eQ, 0);           // qproj ready for fused epilogue
    mma_gemm<false, 3><<<dim3(Hn / 128, (Bn * Sn) / 128), 128, SMEM_DYN>>>(
        p_enc3, 3072, p_key3, 3072, p_part, 0, Bn * Sn, 3072, eW, nullptr, p_qproj, nullptr);
    softmaxP<<<Bn, Sn>>>(srcpos);
    cudaStreamWaitEvent(0, g_eS2, 0);          // c0, wcat3, xcat_h0, preW*3 ready
    context_kernel<<<dim3(Bn, H2 / 256), 256>>>(enc);
    mma_gemm<false, 0><<<dim3(H4 / 128, 1), 128, SMEM_DYN>>>(
        p_xcat3, 4608, p_wcat3, 4608, p_gconst, H4, Bn, 4608, nullptr, nullptr, nullptr, nullptr);
    mma_gemm<false, 0><<<dim3(Hn / 128, 1), 128, SMEM_DYN>>>(
        p_xcat3, 4608, p_preWc3, 3072, p_ctxP, Hn, Bn, 3072, nullptr, nullptr, nullptr, nullptr);
    cudaStreamWaitEvent(0, g_eEmbW, 0);        // embW ready
    gates_kernel<<<Bn * Tn, Hn>>>(tgt, b_ih, b_hh);
    cudaStreamWaitEvent(0, g_eEmbP, 0);        // embP ready
    mma_gemm<false, 1><<<dim3(Hn / 128, (Bn * Tn) / 128), 128, SMEM_DYN>>>(
        p_h3, 1536, p_preWh3, 1536, out, Hn, Bn * Tn, 1536, nullptr, tgt, p_embP, p_ctxP);

    (void)in_sizes; (void)n_in; (void)out_size;
}

// round 8
// speedup vs baseline: 2.8519x; 1.0883x over previous
#include <cuda_runtime.h>
#include <cuda_bf16.h>
#include <math.h>
#include <stdint.h>

#define Bn 128
#define Tn 256
#define Sn 256
#define Hn 512
#define En 256
#define Vn 10000
#define H2 1024
#define H4 2048

typedef __nv_bfloat16 bf16;
typedef __nv_bfloat162 bf162;

// ---------------- fp32 scratch ----------------
__device__ float g_h0[Bn * Hn];
__device__ float g_c0[Bn * Hn];
__device__ float g_qproj[Bn * Hn];
__device__ float g_part[Bn * Sn * 4];
__device__ float g_scores[Bn * Sn];
__device__ float g_gpart[4 * Bn * H4];
__device__ float g_gconst[Bn * H4];
__device__ float g_ctxP[Bn * Hn];
__device__ float g_embW[(size_t)Vn * H4];
__device__ float g_embP[(size_t)Vn * Hn];

// ---------------- blocked hi/lo bf16 operands ----------------
__device__ bf16 g_emb_h[(size_t)Vn * En],   g_emb_l[(size_t)Vn * En];
__device__ bf16 g_Wih_h[(size_t)H4 * En],   g_Wih_l[(size_t)H4 * En];
__device__ bf16 g_pWe_h[(size_t)Hn * En],   g_pWe_l[(size_t)Hn * En];
__device__ bf16 g_key_h[(size_t)Hn * H2],   g_key_l[(size_t)Hn * H2];
__device__ bf16 g_enc_h[(size_t)Bn * Sn * H2], g_enc_l[(size_t)Bn * Sn * H2];
__device__ bf16 g_bhW_h[(size_t)Hn * H2],   g_bhW_l[(size_t)Hn * H2];
__device__ bf16 g_bcW_h[(size_t)Hn * H2],   g_bcW_l[(size_t)Hn * H2];
__device__ bf16 g_qW_h[(size_t)Hn * Hn],    g_qW_l[(size_t)Hn * Hn];
__device__ bf16 g_eh_h[(size_t)Bn * H2],    g_eh_l[(size_t)Bn * H2];
__device__ bf16 g_ec_h[(size_t)Bn * H2],    g_ec_l[(size_t)Bn * H2];
__device__ bf16 g_h0h[(size_t)Bn * Hn],     g_h0l[(size_t)Bn * Hn];
__device__ bf16 g_xc_h[(size_t)Bn * 1536],  g_xc_l[(size_t)Bn * 1536];  // [ctx | h0]
__device__ bf16 g_wc_h[(size_t)H4 * 1536],  g_wc_l[(size_t)H4 * 1536];
__device__ bf16 g_pWh_h[(size_t)Hn * Hn],   g_pWh_l[(size_t)Hn * Hn];
__device__ bf16 g_pWc_h[(size_t)Hn * H2],   g_pWc_l[(size_t)Hn * H2];
__device__ bf16 g_hh[(size_t)Bn * Tn * Hn], g_hl[(size_t)Bn * Tn * Hn];

__device__ __forceinline__ float sigf(float x) { return 1.f / (1.f + expf(-x)); }

// ================= PTX helpers =================
__device__ __forceinline__ uint32_t smem_u32(const void* p) {
    uint32_t a;
    asm("{ .reg .u64 t; cvta.to.shared.u64 t, %1; cvt.u32.u64 %0, t; }" : "=r"(a) : "l"(p));
    return a;
}
__device__ __forceinline__ void cp16(uint32_t dst, const void* src) {
    asm volatile("cp.async.cg.shared.global [%0], [%1], 16;" :: "r"(dst), "l"(src) : "memory");
}
__device__ __forceinline__ void ldsm4(uint32_t* r, uint32_t addr) {
    asm volatile("ldmatrix.sync.aligned.m8n8.x4.shared.b16 {%0,%1,%2,%3}, [%4];"
                 : "=r"(r[0]), "=r"(r[1]), "=r"(r[2]), "=r"(r[3]) : "r"(addr));
}
__device__ __forceinline__ void mma16(float* c, const uint32_t* a, const uint32_t* b) {
    asm volatile("mma.sync.aligned.m16n8k16.row.col.f32.bf16.bf16.f32 "
                 "{%0,%1,%2,%3}, {%4,%5,%6,%7}, {%8,%9}, {%0,%1,%2,%3};"
                 : "+f"(c[0]), "+f"(c[1]), "+f"(c[2]), "+f"(c[3])
                 : "r"(a[0]), "r"(a[1]), "r"(a[2]), "r"(a[3]), "r"(b[0]), "r"(b[1]));
}

// ================= blocked-split bf16 GEMM-NT =================
// C = A*W^T over K' = 3K: pass0 (Ahi,Whi), pass1 (Alo,Whi), pass2 (Ahi,Wlo)
#define NSTAGE 3
#define STAGE_BYTES 32768
#define SMEM_DYN (NSTAGE * STAGE_BYTES)

__device__ __forceinline__ void load_tiles(uint32_t base,
                                           const bf16* __restrict__ A, int lda,
                                           const bf16* __restrict__ W, int ldw,
                                           int m0, int n0, int k0, int M, bool guard, int tid)
{
    uint32_t ab = base, bb = base + 16384u;
    #pragma unroll
    for (int i = 0; i < 8; i++) {
        int c = tid + i * 128;
        int row = c >> 3, c16 = c & 7;
        uint32_t off = (uint32_t)(row * 128) + (uint32_t)((c16 ^ (row & 7)) << 4);
        int ar = m0 + row;
        if (guard && ar >= M) ar = M - 1;
        cp16(ab + off, A + (size_t)ar * lda + k0 + c16 * 8);
        cp16(bb + off, W + (size_t)(n0 + row) * ldw + k0 + c16 * 8);
    }
    asm volatile("cp.async.commit_group;" ::: "memory");
}

// EPI: 0 none; 1 +embP[tok]+ctxP; 2 tanh(acc+bias); 3 fused attention partials;
//      4 split-K partial (C offset by blockIdx.z*M rows)
template<bool GUARD, int EPI>
__global__ __launch_bounds__(128, 2)
void mma_gemm(const bf16* __restrict__ Ah, const bf16* __restrict__ Al, int lda,
              const bf16* __restrict__ Wh, const bf16* __restrict__ Wl, int ldw,
              float* __restrict__ C, int ldc,
              int M, int K, int nkc,
              const float* __restrict__ bias,
              const int* __restrict__ tok,
              const float* __restrict__ embP,
              const float* __restrict__ ctxP)
{
    extern __shared__ char dsm[];
    uint32_t sb = smem_u32(dsm);
    const int tid = threadIdx.x, wid = tid >> 5, lane = tid & 31;
    const int wm = wid & 1, wn = wid >> 1;        // warp tile 64x64
    const int m0 = blockIdx.y * 128, n0 = blockIdx.x * 128;
    const int kb = blockIdx.z * nkc;
    const int per = K >> 6;

    float acc[4][8][4];
    #pragma unroll
    for (int i = 0; i < 4; i++)
        #pragma unroll
        for (int j = 0; j < 8; j++)
            #pragma unroll
            for (int r = 0; r < 4; r++) acc[i][j][r] = 0.f;

    auto chunk = [&](int g, const bf16*& A, const bf16*& W, int& k0) {
        int p = g / per, r = g - p * per;
        k0 = r << 6;
        A = (p == 1) ? Al : Ah;
        W = (p == 2) ? Wl : Wh;
    };

    {
        const bf16 *A, *W; int k0;
        chunk(kb, A, W, k0);
        load_tiles(sb, A, lda, W, ldw, m0, n0, k0, M, GUARD, tid);
        chunk(kb + 1, A, W, k0);
        load_tiles(sb + STAGE_BYTES, A, lda, W, ldw, m0, n0, k0, M, GUARD, tid);
    }

    const int a_mi = lane >> 3, a_r = lane & 7;
    const int b_grp = lane >> 3, b_r = lane & 7;

    for (int j = 0; j < nkc; j++) {
        int nst = j + NSTAGE - 1;
        if (nst < nkc) {
            asm volatile("cp.async.wait_group %0;" :: "n"(NSTAGE - 2) : "memory");
            __syncthreads();
            const bf16 *A, *W; int k0;
            chunk(kb + nst, A, W, k0);
            load_tiles(sb + (uint32_t)(nst % NSTAGE) * STAGE_BYTES,
                       A, lda, W, ldw, m0, n0, k0, M, GUARD, tid);
        } else {
            asm volatile("cp.async.wait_group 0;" ::: "memory");   // tail drain
            __syncthreads();
        }

        uint32_t abase = sb + (uint32_t)(j % NSTAGE) * STAGE_BYTES;
        uint32_t bbase = abase + 16384u;
        #pragma unroll
        for (int k16 = 0; k16 < 4; k16++) {
            uint32_t af[4][4];
            #pragma unroll
            for (int mt = 0; mt < 4; mt++) {
                int row = wm * 64 + mt * 16 + ((a_mi & 1) << 3) + a_r;
                int c16 = (k16 << 1) + (a_mi >> 1);
                ldsm4(af[mt], abase + (uint32_t)(row * 128) + (uint32_t)((c16 ^ (row & 7)) << 4));
            }
            uint32_t bfl[16];
            #pragma unroll
            for (int p = 0; p < 4; p++) {
                int row = wn * 64 + p * 16 + ((b_grp >> 1) << 3) + b_r;
                int c16 = (k16 << 1) + (b_grp & 1);
                ldsm4(&bfl[p * 4], bbase + (uint32_t)(row * 128) + (uint32_t)((c16 ^ (row & 7)) << 4));
            }
            #pragma unroll
            for (int mt = 0; mt < 4; mt++)
                #pragma unroll
                for (int nt = 0; nt < 8; nt++)
                    mma16(acc[mt][nt], af[mt], &bfl[nt * 2]);
        }
    }

    if (EPI == 3) {
        __syncthreads();
        float* sred = reinterpret_cast<float*>(dsm);
        #pragma unroll
        for (int mt = 0; mt < 4; mt++) {
            #pragma unroll
            for (int half = 0; half < 2; half++) {
                int rl = wm * 64 + mt * 16 + (lane >> 2) + half * 8;
                int row = m0 + rl;
                const float* q = embP + (size_t)(row >> 8) * Hn;   // qproj
                float p = 0.f;
                #pragma unroll
                for (int nt = 0; nt < 8; nt++) {
                    int col = n0 + wn * 64 + nt * 8 + (lane & 3) * 2;
                    p += tanhf(acc[mt][nt][half * 2]     + q[col])     * bias[col];
                    p += tanhf(acc[mt][nt][half * 2 + 1] + q[col + 1]) * bias[col + 1];
                }
                p += __shfl_xor_sync(0xffffffffu, p, 1);
                p += __shfl_xor_sync(0xffffffffu, p, 2);
                if ((lane & 3) == 0) sred[rl * 2 + wn] = p;
            }
        }
        __syncthreads();
        if (tid < 128)
            C[(size_t)(m0 + tid) * 4 + blockIdx.x] = sred[tid * 2] + sred[tid * 2 + 1];
        return;
    }

    size_t zoff = (EPI == 4) ? (size_t)blockIdx.z * M : 0;
    #pragma unroll
    for (int mt = 0; mt < 4; mt++) {
        #pragma unroll
        for (int half = 0; half < 2; half++) {
            int row = m0 + wm * 64 + mt * 16 + (lane >> 2) + half * 8;
            if (GUARD && row >= M) continue;
            const float* ep = nullptr; const float* cq = nullptr;
            if (EPI == 1) {
                ep = embP + (size_t)tok[row] * Hn;
                cq = ctxP + (size_t)(row >> 8) * Hn;
            }
            #pragma unroll
            for (int nt = 0; nt < 8; nt++) {
                int col = n0 + wn * 64 + nt * 8 + (lane & 3) * 2;
                float vx = acc[mt][nt][half * 2];
                float vy = acc[mt][nt][half * 2 + 1];
                if (EPI == 1) {
                    vx += ep[col] + cq[col];
                    vy += ep[col + 1] + cq[col + 1];
                }
                if (EPI == 2) {
                    vx = tanhf(vx + bias[col]);
                    vy = tanhf(vy + bias[col + 1]);
                }
                *reinterpret_cast<float2*>(C + (zoff + row) * ldc + col) = make_float2(vx, vy);
            }
        }
    }
}

// ================= fp32 -> blocked hi/lo =================
__global__ void cvt2_kernel(const float* __restrict__ src, int lds,
                            bf16* __restrict__ dhi, bf16* __restrict__ dlo, int K)
{
    int row = blockIdx.x;
    const float* s = src + (size_t)row * lds;
    bf162* dh = reinterpret_cast<bf162*>(dhi + (size_t)row * K);
    bf162* dl = reinterpret_cast<bf162*>(dlo + (size_t)row * K);
    for (int k4 = threadIdx.x; k4 < K / 4; k4 += blockDim.x) {
        float4 v = *reinterpret_cast<const float4*>(s + k4 * 4);
        float a[4] = {v.x, v.y, v.z, v.w};
        bf162 h2[2], l2[2];
        #pragma unroll
        for (int i = 0; i < 4; i++) {
            bf16 h = __float2bfloat16(a[i]);
            bf16 l = __float2bfloat16(a[i] - __bfloat162float(h));
            if (i & 1) { h2[i >> 1].y = h; l2[i >> 1].y = l; }
            else       { h2[i >> 1].x = h; l2[i >> 1].x = l; }
        }
        dh[k4 * 2] = h2[0]; dh[k4 * 2 + 1] = h2[1];
        dl[k4 * 2] = l2[0]; dl[k4 * 2 + 1] = l2[1];
    }
}

// wcat hi/lo[n][1536] = split of [W_ih[n, E:] | W_hh[n, :]]
__global__ void pack_wcat2(const float* __restrict__ W_ih, const float* __restrict__ W_hh) {
    int n = blockIdx.x;
    bf16* dh = g_wc_h + (size_t)n * 1536;
    bf16* dl = g_wc_l + (size_t)n * 1536;
    const float* wi = W_ih + (size_t)n * (En + H2) + En;
    const float* wh = W_hh + (size_t)n * Hn;
    for (int k = threadIdx.x; k < 1536; k += blockDim.x) {
        float a = (k < H2) ? wi[k] : wh[k - H2];
        bf16 h = __float2bfloat16(a);
        dh[k] = h;
        dl[k] = __float2bfloat16(a - __bfloat162float(h));
    }
}
// xcat tail [1024:1536] = split of h0
__global__ void xcat_h0() {
    int b = blockIdx.x;
    for (int k = threadIdx.x; k < Hn; k += blockDim.x) {
        float a = g_h0[(size_t)b * Hn + k];
        bf16 h = __float2bfloat16(a);
        g_xc_h[(size_t)b * 1536 + H2 + k] = h;
        g_xc_l[(size_t)b * 1536 + H2 + k] = __float2bfloat16(a - __bfloat162float(h));
    }
}

// ================= attention small kernels =================
__global__ void softmaxP(const int* __restrict__ srcpos) {
    __shared__ float sm[8];
    int b = blockIdx.x, t = threadIdx.x, w = t >> 5, l = t & 31;
    int row = b * Sn + t;
    float4 pp = *reinterpret_cast<const float4*>(g_part + (size_t)row * 4);
    float v = (srcpos[row] != 0) ? (pp.x + pp.y + pp.z + pp.w) : -1e9f;
    float m = v;
    #pragma unroll
    for (int o = 16; o; o >>= 1) m = fmaxf(m, __shfl_xor_sync(0xffffffffu, m, o));
    if (l == 0) sm[w] = m;
    __syncthreads();
    m = sm[0];
    #pragma unroll
    for (int i = 1; i < 8; i++) m = fmaxf(m, sm[i]);
    __syncthreads();
    float e = expf(v - m);
    float s = e;
    #pragma unroll
    for (int o = 16; o; o >>= 1) s += __shfl_xor_sync(0xffffffffu, s, o);
    if (l == 0) sm[w] = s;
    __syncthreads();
    s = 0.f;
    #pragma unroll
    for (int i = 0; i < 8; i++) s += sm[i];
    g_scores[row] = e / s;
}

// context -> xcat[0:1024] hi/lo
__global__ void context_kernel(const float* __restrict__ enc) {
    __shared__ float a[Sn];
    int b = blockIdx.x;
    int d = blockIdx.y * 256 + threadIdx.x;
    a[threadIdx.x] = g_scores[b * Sn + threadIdx.x];
    __syncthreads();
    const float* e = enc + (size_t)b * Sn * H2 + d;
    float s = 0.f;
    #pragma unroll 4
    for (int sS = 0; sS < Sn; sS++) s += a[sS] * e[(size_t)sS * H2];
    bf16 h = __float2bfloat16(s);
    g_xc_h[(size_t)b * 1536 + d] = h;
    g_xc_l[(size_t)b * 1536 + d] = __float2bfloat16(s - __bfloat162float(h));
}

// gconst = deterministic sum of 4 split-K partials
__global__ void reduce4() {
    int i = blockIdx.x * 256 + threadIdx.x;
    const int N = Bn * H4;
    g_gconst[i] = (g_gpart[i] + g_gpart[i + N]) + (g_gpart[i + 2 * N] + g_gpart[i + 3 * N]);
}

// LSTM cell -> h hi/lo (256 threads, cols 2t, 2t+1)
__global__ void gates_kernel(const int* __restrict__ tgt,
                             const float* __restrict__ b_ih,
                             const float* __restrict__ b_hh) {
    int row = blockIdx.x;
    int t = threadIdx.x;
    int b = row >> 8;
    int tok = tgt[row];
    const float2* ew = reinterpret_cast<const float2*>(g_embW + (size_t)tok * H4);
    const float2* gc = reinterpret_cast<const float2*>(g_gconst + (size_t)b * H4);
    const float2* bi = reinterpret_cast<const float2*>(b_ih);
    const float2* bh = reinterpret_cast<const float2*>(b_hh);
    const float2* c0 = reinterpret_cast<const float2*>(g_c0 + (size_t)b * Hn);
    float2 e0 = ew[t],       g0 = gc[t],       q0 = bi[t],       r0 = bh[t];
    float2 e1 = ew[t + 256], g1 = gc[t + 256], q1 = bi[t + 256], r1 = bh[t + 256];
    float2 e2 = ew[t + 512], g2 = gc[t + 512], q2 = bi[t + 512], r2 = bh[t + 512];
    float2 e3 = ew[t + 768], g3 = gc[t + 768], q3 = bi[t + 768], r3 = bh[t + 768];
    float2 cv = c0[t];
    float ix = e0.x + g0.x + q0.x + r0.x, iy = e0.y + g0.y + q0.y + r0.y;
    float fx = e1.x + g1.x + q1.x + r1.x, fy = e1.y + g1.y + q1.y + r1.y;
    float gx = e2.x + g2.x + q2.x + r2.x, gy = e2.y + g2.y + q2.y + r2.y;
    float ox = e3.x + g3.x + q3.x + r3.x, oy = e3.y + g3.y + q3.y + r3.y;
    float cx = sigf(fx) * cv.x + sigf(ix) * tanhf(gx);
    float cy = sigf(fy) * cv.y + sigf(iy) * tanhf(gy);
    float hx = sigf(ox) * tanhf(cx);
    float hy = sigf(oy) * tanhf(cy);
    bf162 vh, vl;
    vh.x = __float2bfloat16(hx);
    vh.y = __float2bfloat16(hy);
    vl.x = __float2bfloat16(hx - __bfloat162float(vh.x));
    vl.y = __float2bfloat16(hy - __bfloat162float(vh.y));
    reinterpret_cast<bf162*>(g_hh + (size_t)row * Hn)[t] = vh;
    reinterpret_cast<bf162*>(g_hl + (size_t)row * Hn)[t] = vl;
}

// ================= stream/event setup (host resources only) =================
static cudaStream_t g_s1, g_s2;
static cudaEvent_t g_eFork, g_eS2, g_eQ, g_eEmbW, g_eEmbP, g_eCtx, g_eCtxP;
namespace {
struct StreamInit {
    StreamInit() {
        cudaStreamCreateWithFlags(&g_s1, cudaStreamNonBlocking);
        cudaStreamCreateWithFlags(&g_s2, cudaStreamNonBlocking);
        cudaEventCreateWithFlags(&g_eFork, cudaEventDisableTiming);
        cudaEventCreateWithFlags(&g_eS2, cudaEventDisableTiming);
        cudaEventCreateWithFlags(&g_eQ, cudaEventDisableTiming);
        cudaEventCreateWithFlags(&g_eEmbW, cudaEventDisableTiming);
        cudaEventCreateWithFlags(&g_eEmbP, cudaEventDisableTiming);
        cudaEventCreateWithFlags(&g_eCtx, cudaEventDisableTiming);
        cudaEventCreateWithFlags(&g_eCtxP, cudaEventDisableTiming);
    }
} g_streamInit;
}

// =========================================================================================
extern "C" void kernel_launch(void* const* d_in, const int* in_sizes, int n_in,
                              void* d_out, int out_size)
{
    const int*   tgt     = (const int*)  d_in[0];
    const float* enc     = (const float*)d_in[1];
    const float* eh      = (const float*)d_in[2];
    const float* ec      = (const float*)d_in[3];
    const int*   srcpos  = (const int*)  d_in[4];
    const float* emb     = (const float*)d_in[5];
    const float* key_W   = (const float*)d_in[6];
    const float* query_W = (const float*)d_in[7];
    const float* eW      = (const float*)d_in[8];
    const float* W_ih    = (const float*)d_in[9];
    const float* W_hh    = (const float*)d_in[10];
    const float* b_ih    = (const float*)d_in[11];
    const float* b_hh    = (const float*)d_in[12];
    const float* bhW     = (const float*)d_in[13];
    const float* bhb     = (const float*)d_in[14];
    const float* bcW     = (const float*)d_in[15];
    const float* bcb     = (const float*)d_in[16];
    const float* pre_W   = (const float*)d_in[17];
    float* out = (float*)d_out;

    float *p_h0, *p_c0, *p_qproj, *p_part, *p_ctxP, *p_embW, *p_embP, *p_gpart, *p_gconst;
    cudaGetSymbolAddress((void**)&p_h0, g_h0);
    cudaGetSymbolAddress((void**)&p_c0, g_c0);
    cudaGetSymbolAddress((void**)&p_qproj, g_qproj);
    cudaGetSymbolAddress((void**)&p_part, g_part);
    cudaGetSymbolAddress((void**)&p_ctxP, g_ctxP);
    cudaGetSymbolAddress((void**)&p_embW, g_embW);
    cudaGetSymbolAddress((void**)&p_embP, g_embP);
    cudaGetSymbolAddress((void**)&p_gpart, g_gpart);
    cudaGetSymbolAddress((void**)&p_gconst, g_gconst);

    bf16 *eb_h, *eb_l, *wi_h, *wi_l, *pe_h, *pe_l, *ky_h, *ky_l, *en_h, *en_l;
    bf16 *bhh_, *bhl_, *bch_, *bcl_, *qwh, *qwl, *ehh, *ehl, *ech, *ecl;
    bf16 *h0h, *h0l, *xch, *xcl, *wch, *wcl, *phh, *phl, *pch, *pcl, *hh, *hl;
    cudaGetSymbolAddress((void**)&eb_h, g_emb_h); cudaGetSymbolAddress((void**)&eb_l, g_emb_l);
    cudaGetSymbolAddress((void**)&wi_h, g_Wih_h); cudaGetSymbolAddress((void**)&wi_l, g_Wih_l);
    cudaGetSymbolAddress((void**)&pe_h, g_pWe_h); cudaGetSymbolAddress((void**)&pe_l, g_pWe_l);
    cudaGetSymbolAddress((void**)&ky_h, g_key_h); cudaGetSymbolAddress((void**)&ky_l, g_key_l);
    cudaGetSymbolAddress((void**)&en_h, g_enc_h); cudaGetSymbolAddress((void**)&en_l, g_enc_l);
    cudaGetSymbolAddress((void**)&bhh_, g_bhW_h); cudaGetSymbolAddress((void**)&bhl_, g_bhW_l);
    cudaGetSymbolAddress((void**)&bch_, g_bcW_h); cudaGetSymbolAddress((void**)&bcl_, g_bcW_l);
    cudaGetSymbolAddress((void**)&qwh, g_qW_h);   cudaGetSymbolAddress((void**)&qwl, g_qW_l);
    cudaGetSymbolAddress((void**)&ehh, g_eh_h);   cudaGetSymbolAddress((void**)&ehl, g_eh_l);
    cudaGetSymbolAddress((void**)&ech, g_ec_h);   cudaGetSymbolAddress((void**)&ecl, g_ec_l);
    cudaGetSymbolAddress((void**)&h0h, g_h0h);    cudaGetSymbolAddress((void**)&h0l, g_h0l);
    cudaGetSymbolAddress((void**)&xch, g_xc_h);   cudaGetSymbolAddress((void**)&xcl, g_xc_l);
    cudaGetSymbolAddress((void**)&wch, g_wc_h);   cudaGetSymbolAddress((void**)&wcl, g_wc_l);
    cudaGetSymbolAddress((void**)&phh, g_pWh_h);  cudaGetSymbolAddress((void**)&phl, g_pWh_l);
    cudaGetSymbolAddress((void**)&pch, g_pWc_h);  cudaGetSymbolAddress((void**)&pcl, g_pWc_l);
    cudaGetSymbolAddress((void**)&hh, g_hh);      cudaGetSymbolAddress((void**)&hl, g_hl);

    cudaFuncSetAttribute(mma_gemm<false, 0>, cudaFuncAttributeMaxDynamicSharedMemorySize, SMEM_DYN);
    cudaFuncSetAttribute(mma_gemm<false, 1>, cudaFuncAttributeMaxDynamicSharedMemorySize, SMEM_DYN);
    cudaFuncSetAttribute(mma_gemm<false, 2>, cudaFuncAttributeMaxDynamicSharedMemorySize, SMEM_DYN);
    cudaFuncSetAttribute(mma_gemm<false, 3>, cudaFuncAttributeMaxDynamicSharedMemorySize, SMEM_DYN);
    cudaFuncSetAttribute(mma_gemm<false, 4>, cudaFuncAttributeMaxDynamicSharedMemorySize, SMEM_DYN);
    cudaFuncSetAttribute(mma_gemm<true, 0>,  cudaFuncAttributeMaxDynamicSharedMemorySize, SMEM_DYN);

    // ---- fork ----
    cudaEventRecord(g_eFork, 0);
    cudaStreamWaitEvent(g_s1, g_eFork, 0);
    cudaStreamWaitEvent(g_s2, g_eFork, 0);

    // ===== s1: vocab precomputes =====
    cvt2_kernel<<<Vn, 64, 0, g_s1>>>(emb, En, eb_h, eb_l, En);
    cvt2_kernel<<<H4, 64, 0, g_s1>>>(W_ih, En + H2, wi_h, wi_l, En);
    cvt2_kernel<<<Hn, 64, 0, g_s1>>>(pre_W, En + Hn + H2, pe_h, pe_l, En);
    mma_gemm<true, 0><<<dim3(H4 / 128, (Vn + 127) / 128), 128, SMEM_DYN, g_s1>>>(
        eb_h, eb_l, En, wi_h, wi_l, En, p_embW, H4, Vn, En, 12, nullptr, nullptr, nullptr, nullptr);
    cudaEventRecord(g_eEmbW, g_s1);
    mma_gemm<true, 0><<<dim3(Hn / 128, (Vn + 127) / 128), 128, SMEM_DYN, g_s1>>>(
        eb_h, eb_l, En, pe_h, pe_l, En, p_embP, Hn, Vn, En, 12, nullptr, nullptr, nullptr, nullptr);
    cudaEventRecord(g_eEmbP, g_s1);

    // ===== s2: qproj chain first, then remaining weights =====
    cvt2_kernel<<<Hn, 128, 0, g_s2>>>(bhW, H2, bhh_, bhl_, H2);
    cvt2_kernel<<<Bn, 128, 0, g_s2>>>(eh, H2, ehh, ehl, H2);
    cvt2_kernel<<<Hn, 128, 0, g_s2>>>(query_W, Hn, qwh, qwl, Hn);
    mma_gemm<false, 2><<<dim3(Hn / 128, 1), 128, SMEM_DYN, g_s2>>>(
        ehh, ehl, H2, bhh_, bhl_, H2, p_h0, Hn, Bn, H2, 48, bhb, nullptr, nullptr, nullptr);
    cvt2_kernel<<<Bn, 128, 0, g_s2>>>(p_h0, Hn, h0h, h0l, Hn);
    mma_gemm<false, 0><<<dim3(Hn / 128, 1), 128, SMEM_DYN, g_s2>>>(
        h0h, h0l, Hn, qwh, qwl, Hn, p_qproj, Hn, Bn, Hn, 24, nullptr, nullptr, nullptr, nullptr);
    cudaEventRecord(g_eQ, g_s2);
    xcat_h0<<<Bn, 256, 0, g_s2>>>();
    cvt2_kernel<<<Hn, 128, 0, g_s2>>>(bcW, H2, bch_, bcl_, H2);
    cvt2_kernel<<<Bn, 128, 0, g_s2>>>(ec, H2, ech, ecl, H2);
    mma_gemm<false, 2><<<dim3(Hn / 128, 1), 128, SMEM_DYN, g_s2>>>(
        ech, ecl, H2, bch_, bcl_, H2, p_c0, Hn, Bn, H2, 48, bcb, nullptr, nullptr, nullptr);
    pack_wcat2<<<H4, 256, 0, g_s2>>>(W_ih, W_hh);
    cvt2_kernel<<<Hn, 128, 0, g_s2>>>(pre_W + En, En + Hn + H2, phh, phl, Hn);
    cvt2_kernel<<<Hn, 128, 0, g_s2>>>(pre_W + En + Hn, En + Hn + H2, pch, pcl, H2);
    cudaEventRecord(g_eS2, g_s2);

    // ===== s0: attention critical path (up through context) =====
    cvt2_kernel<<<Hn, 128>>>(key_W, H2, ky_h, ky_l, H2);
    cvt2_kernel<<<Bn * Sn, 128>>>(enc, H2, en_h, en_l, H2);
    cudaStreamWaitEvent(0, g_eQ, 0);
    mma_gemm<false, 3><<<dim3(Hn / 128, (Bn * Sn) / 128), 128, SMEM_DYN>>>(
        en_h, en_l, H2, ky_h, ky_l, H2, p_part, 0, Bn * Sn, H2, 48, eW, nullptr, p_qproj, nullptr);
    softmaxP<<<Bn, Sn>>>(srcpos);
    cudaStreamWaitEvent(0, g_eS2, 0);
    context_kernel<<<dim3(Bn, H2 / 256), 256>>>(enc);
    cudaEventRecord(g_eCtx, 0);

    // ===== s2 continuation: ctxP concurrent with gconst (record-before-wait in host order) =====
    cudaStreamWaitEvent(g_s2, g_eCtx, 0);
    mma_gemm<false, 0><<<dim3(Hn / 128, 1), 128, SMEM_DYN, g_s2>>>(
        xch, xcl, 1536, pch, pcl, H2, p_ctxP, Hn, Bn, H2, 48, nullptr, nullptr, nullptr, nullptr);
    cudaEventRecord(g_eCtxP, g_s2);

    // ===== s0 continuation =====
    mma_gemm<false, 4><<<dim3(H4 / 128, 1, 4), 128, SMEM_DYN>>>(
        xch, xcl, 1536, wch, wcl, 1536, p_gpart, H4, Bn, 1536, 18, nullptr, nullptr, nullptr, nullptr);
    reduce4<<<(Bn * H4) / 256, 256>>>();
    cudaStreamWaitEvent(0, g_eEmbW, 0);
    gates_kernel<<<Bn * Tn, 256>>>(tgt, b_ih, b_hh);
    cudaStreamWaitEvent(0, g_eEmbP, 0);
    cudaStreamWaitEvent(0, g_eCtxP, 0);
    mma_gemm<false, 1><<<dim3(Hn / 128, (Bn * Tn) / 128), 128, SMEM_DYN>>>(
        hh, hl, Hn, phh, phl, Hn, out, Hn, Bn * Tn, Hn, 24, nullptr, tgt, p_embP, p_ctxP);

    (void)in_sizes; (void)n_in; (void)out_size;
}